// round 2
// baseline (speedup 1.0000x reference)
#include <cuda_runtime.h>
#include <cmath>

#define IMG 128
#define CH 256
#define NTOK 16384
#define NHEADS 8
#define DHE 64
#define NF 256
#define NBH 32
#define MTOT 65536
#define DN 0.3535533905932738f
#define RATIO 0.0625f
#define FEPS 1e-4f

// ---------------- device scratch (static, allocation-free) ----------------
__device__ float g_q[33554432];      // [32][16384][64]
__device__ float g_k[33554432];
__device__ float g_v[33554432];
__device__ float g_qp[134217728];    // [32][16384][256]
__device__ float g_kp[134217728];    // dd then kp in-place
__device__ float g_attn[33554432];   // [65536][512] head-concat
__device__ float g_y1[16777216];     // [65536][256]
__device__ float g_projT[16384];     // [64][256]
__device__ float g_diag[524288];     // [32][16384]
__device__ float g_kmax_part[16384]; // [32][512]
__device__ float g_kmax[32];
__device__ float g_ksum[8192];       // [32][256]
__device__ float g_ctx[524288];      // [32][256][64]

// ---------------- tiny prep kernels ----------------
__global__ void transpose_proj(const float* __restrict__ proj) {
    int idx = blockIdx.x * 256 + threadIdx.x;
    if (idx < 16384) {
        int f = idx >> 6, d = idx & 63;
        g_projT[d * 256 + f] = proj[idx];
    }
}

__global__ void zero_accum() {
    int idx = blockIdx.x * 256 + threadIdx.x;
    if (idx < 524288) g_ctx[idx] = 0.f;
    else if (idx < 524288 + 8192) g_ksum[idx - 524288] = 0.f;
}

// ---------------- QKV fused GEMM: [65536x256] @ [256x512] x3 ----------------
// BM=128, BN=64 (== one head), BK=16, 256 threads, 8x4 per-thread tile.
__global__ void __launch_bounds__(256) qkv_gemm(const float* __restrict__ x,
                                                const float* __restrict__ Wq,
                                                const float* __restrict__ Wk,
                                                const float* __restrict__ Wv) {
    __shared__ float As[16][132];
    __shared__ float Bs[16][64];
    const float* W = blockIdx.z == 0 ? Wq : (blockIdx.z == 1 ? Wk : Wv);
    float* outb = blockIdx.z == 0 ? g_q : (blockIdx.z == 1 ? g_k : g_v);
    const int h = blockIdx.x;              // col tile == head
    const int row0 = blockIdx.y * 128;
    const int tid = threadIdx.x;
    const int tm = tid >> 4, tn = tid & 15;
    const int a_m = tid >> 1, a_k = (tid & 1) << 3;
    const int b_k = tid >> 4, b_n = (tid & 15) << 2;
    float acc[8][4];
#pragma unroll
    for (int i = 0; i < 8; i++)
#pragma unroll
        for (int j = 0; j < 4; j++) acc[i][j] = 0.f;

    for (int k0 = 0; k0 < CH; k0 += 16) {
        const float* ap = x + (size_t)(row0 + a_m) * CH + k0 + a_k;
        float4 av0 = *(const float4*)ap;
        float4 av1 = *(const float4*)(ap + 4);
        As[a_k + 0][a_m] = av0.x; As[a_k + 1][a_m] = av0.y;
        As[a_k + 2][a_m] = av0.z; As[a_k + 3][a_m] = av0.w;
        As[a_k + 4][a_m] = av1.x; As[a_k + 5][a_m] = av1.y;
        As[a_k + 6][a_m] = av1.z; As[a_k + 7][a_m] = av1.w;
        *(float4*)&Bs[b_k][b_n] =
            *(const float4*)(W + (size_t)(k0 + b_k) * 512 + h * 64 + b_n);
        __syncthreads();
#pragma unroll
        for (int kk = 0; kk < 16; kk++) {
            float a[8], b[4];
            *(float4*)(a)     = *(const float4*)&As[kk][tm * 8];
            *(float4*)(a + 4) = *(const float4*)&As[kk][tm * 8 + 4];
            *(float4*)(b)     = *(const float4*)&Bs[kk][tn * 4];
#pragma unroll
            for (int i = 0; i < 8; i++)
#pragma unroll
                for (int j = 0; j < 4; j++) acc[i][j] += a[i] * b[j];
        }
        __syncthreads();
    }
#pragma unroll
    for (int i = 0; i < 8; i++) {
        int r = row0 + tm * 8 + i;
        int b = r >> 14, n = r & (NTOK - 1);
        float4 v = make_float4(acc[i][0], acc[i][1], acc[i][2], acc[i][3]);
        *(float4*)(outb + ((size_t)((b << 3) | h) * NTOK + n) * 64 + tn * 4) = v;
    }
}

// ---------------- phi: dd = (q*dn) @ projT, + softmax-kernel epilogue ----------------
// Block: 32 rows x 256 features; thread (tm,tn): rows {2tm,2tm+1}, f = jb*64+tn*4+j.
__global__ void __launch_bounds__(256) phi_kernel(int is_query) {
    extern __shared__ float sm[];
    float* s_projT = sm;               // 64*256
    float* s_q     = sm + 16384;       // 32*64
    float* s_red   = sm + 18432;       // 8
    const int tid = threadIdx.x;
    const int bh = blockIdx.y;
    const int row_base = blockIdx.x * 32;
    const float* src = is_query ? g_q : g_k;
    float* dst = is_query ? g_qp : g_kp;

#pragma unroll
    for (int i = 0; i < 16; i++)
        ((float4*)s_projT)[tid + i * 256] = ((const float4*)g_projT)[tid + i * 256];
    {
        const float4* qb = (const float4*)(src + ((size_t)bh * NTOK + row_base) * 64);
#pragma unroll
        for (int i = 0; i < 2; i++) {
            float4 v = qb[tid + i * 256];
            v.x *= DN; v.y *= DN; v.z *= DN; v.w *= DN;
            ((float4*)s_q)[tid + i * 256] = v;
        }
    }
    __syncthreads();

    const int tm = tid >> 4, tn = tid & 15;
    float acc0[16], acc1[16];
#pragma unroll
    for (int i = 0; i < 16; i++) { acc0[i] = 0.f; acc1[i] = 0.f; }
    float dg0 = 0.f, dg1 = 0.f;
    const float* q0 = s_q + (2 * tm) * 64;
    const float* q1 = q0 + 64;
#pragma unroll 4
    for (int d = 0; d < 64; d++) {
        float a0 = q0[d], a1 = q1[d];
        dg0 += a0 * a0; dg1 += a1 * a1;
#pragma unroll
        for (int jb = 0; jb < 4; jb++) {
            float4 p = *(const float4*)&s_projT[d * 256 + jb * 64 + tn * 4];
            acc0[jb*4+0] += a0 * p.x; acc0[jb*4+1] += a0 * p.y;
            acc0[jb*4+2] += a0 * p.z; acc0[jb*4+3] += a0 * p.w;
            acc1[jb*4+0] += a1 * p.x; acc1[jb*4+1] += a1 * p.y;
            acc1[jb*4+2] += a1 * p.z; acc1[jb*4+3] += a1 * p.w;
        }
    }
    float diag0 = 0.5f * dg0, diag1 = 0.5f * dg1;
    size_t base0 = ((size_t)bh * NTOK + row_base + 2 * tm) * 256;
    size_t base1 = base0 + 256;

    if (is_query) {
        float m0 = -1e30f, m1 = -1e30f;
#pragma unroll
        for (int i = 0; i < 16; i++) { m0 = fmaxf(m0, acc0[i]); m1 = fmaxf(m1, acc1[i]); }
#pragma unroll
        for (int o = 1; o < 16; o <<= 1) {
            m0 = fmaxf(m0, __shfl_xor_sync(0xffffffffu, m0, o));
            m1 = fmaxf(m1, __shfl_xor_sync(0xffffffffu, m1, o));
        }
#pragma unroll
        for (int jb = 0; jb < 4; jb++) {
            float4 o0, o1;
            o0.x = RATIO * (expf(acc0[jb*4+0] - diag0 - m0) + FEPS);
            o0.y = RATIO * (expf(acc0[jb*4+1] - diag0 - m0) + FEPS);
            o0.z = RATIO * (expf(acc0[jb*4+2] - diag0 - m0) + FEPS);
            o0.w = RATIO * (expf(acc0[jb*4+3] - diag0 - m0) + FEPS);
            o1.x = RATIO * (expf(acc1[jb*4+0] - diag1 - m1) + FEPS);
            o1.y = RATIO * (expf(acc1[jb*4+1] - diag1 - m1) + FEPS);
            o1.z = RATIO * (expf(acc1[jb*4+2] - diag1 - m1) + FEPS);
            o1.w = RATIO * (expf(acc1[jb*4+3] - diag1 - m1) + FEPS);
            *(float4*)(dst + base0 + jb * 64 + tn * 4) = o0;
            *(float4*)(dst + base1 + jb * 64 + tn * 4) = o1;
        }
    } else {
#pragma unroll
        for (int jb = 0; jb < 4; jb++) {
            *(float4*)(dst + base0 + jb * 64 + tn * 4) =
                make_float4(acc0[jb*4+0], acc0[jb*4+1], acc0[jb*4+2], acc0[jb*4+3]);
            *(float4*)(dst + base1 + jb * 64 + tn * 4) =
                make_float4(acc1[jb*4+0], acc1[jb*4+1], acc1[jb*4+2], acc1[jb*4+3]);
        }
        float bm = -1e30f;
#pragma unroll
        for (int i = 0; i < 16; i++) { bm = fmaxf(bm, acc0[i]); bm = fmaxf(bm, acc1[i]); }
#pragma unroll
        for (int o = 1; o < 32; o <<= 1) bm = fmaxf(bm, __shfl_xor_sync(0xffffffffu, bm, o));
        if ((tid & 31) == 0) s_red[tid >> 5] = bm;
        __syncthreads();
        if (tid == 0) {
            float m = s_red[0];
#pragma unroll
            for (int w = 1; w < 8; w++) m = fmaxf(m, s_red[w]);
            g_kmax_part[bh * 512 + blockIdx.x] = m;
        }
        if (tn == 0) {
            g_diag[(size_t)bh * NTOK + row_base + 2 * tm] = diag0;
            g_diag[(size_t)bh * NTOK + row_base + 2 * tm + 1] = diag1;
        }
    }
}

__global__ void kmax_reduce() {
    __shared__ float s[8];
    int bh = blockIdx.x, tid = threadIdx.x;
    float v = fmaxf(g_kmax_part[bh * 512 + tid], g_kmax_part[bh * 512 + 256 + tid]);
#pragma unroll
    for (int o = 1; o < 32; o <<= 1) v = fmaxf(v, __shfl_xor_sync(0xffffffffu, v, o));
    if ((tid & 31) == 0) s[tid >> 5] = v;
    __syncthreads();
    if (tid == 0) {
        float m = s[0];
#pragma unroll
        for (int w = 1; w < 8; w++) m = fmaxf(m, s[w]);
        g_kmax[bh] = m;
    }
}

// kp = ratio*(exp(dd - diag - m)+eps), in-place; accumulate ksum columns
__global__ void __launch_bounds__(256) kp_finalize() {
    const int bh = blockIdx.y, chunk = blockIdx.x, tid = threadIdx.x;
    const float m = g_kmax[bh];
    float lsum = 0.f;
    size_t rb = (size_t)bh * NTOK + chunk * 32;
#pragma unroll 4
    for (int r = 0; r < 32; r++) {
        float dia = g_diag[rb + r];
        size_t idx = (rb + r) * 256 + tid;
        float dd = g_kp[idx];
        float kp = RATIO * (expf(dd - dia - m) + FEPS);
        g_kp[idx] = kp;
        lsum += kp;
    }
    atomicAdd(&g_ksum[bh * 256 + tid], lsum);
}

// ---------------- context[bh][f][d] = sum_n kp[n][f] * v[n][d] ----------------
__global__ void __launch_bounds__(256) ctx_kernel() {
    __shared__ float s_kp[16 * 256];
    __shared__ float s_v[16 * 68];
    const int tid = threadIdx.x;
    const int bh = blockIdx.y;
    const int chunk = blockIdx.x;        // 16 chunks x 1024 rows
    const int fb = tid >> 4, db = tid & 15;
    const int f0 = fb * 16, d0 = db * 4;
    float acc[16][4];
#pragma unroll
    for (int i = 0; i < 16; i++)
#pragma unroll
        for (int j = 0; j < 4; j++) acc[i][j] = 0.f;

    const float4* kp4 = (const float4*)g_kp;
    const float4* v4 = (const float4*)g_v;
    for (int t = 0; t < 64; t++) {
        size_t gr = (size_t)bh * NTOK + chunk * 1024 + t * 16;
#pragma unroll
        for (int i = 0; i < 4; i++) {
            int u = tid + i * 256;
            ((float4*)s_kp)[u] = kp4[(gr + (u >> 6)) * 64 + (u & 63)];
        }
        {
            int u = tid;
            *(float4*)&s_v[(u >> 4) * 68 + (u & 15) * 4] = v4[(gr + (u >> 4)) * 16 + (u & 15)];
        }
        __syncthreads();
#pragma unroll
        for (int nn = 0; nn < 16; nn++) {
            float4 vv = *(const float4*)&s_v[nn * 68 + d0];
#pragma unroll
            for (int i4 = 0; i4 < 4; i4++) {
                float4 pp = *(const float4*)&s_kp[nn * 256 + f0 + i4 * 4];
                float pv[4] = {pp.x, pp.y, pp.z, pp.w};
#pragma unroll
                for (int ii = 0; ii < 4; ii++) {
                    acc[i4*4+ii][0] += pv[ii] * vv.x;
                    acc[i4*4+ii][1] += pv[ii] * vv.y;
                    acc[i4*4+ii][2] += pv[ii] * vv.z;
                    acc[i4*4+ii][3] += pv[ii] * vv.w;
                }
            }
        }
        __syncthreads();
    }
#pragma unroll
    for (int i = 0; i < 16; i++)
#pragma unroll
        for (int j = 0; j < 4; j++)
            atomicAdd(&g_ctx[((size_t)bh * 256 + f0 + i) * 64 + d0 + j], acc[i][j]);
}

// ---------------- attn = (qp @ ctx) * d_inv, d_inv = 1/(qp . ksum) ----------------
__global__ void __launch_bounds__(256) attn_kernel() {
    extern __shared__ float sm[];
    float* s_ctx = sm;            // 256*64
    float* s_qp  = sm + 16384;    // 32*256
    float* s_ks  = sm + 24576;    // 256
    const int tid = threadIdx.x;
    const int bh = blockIdx.y;
    const int row_base = blockIdx.x * 32;

#pragma unroll
    for (int i = 0; i < 16; i++)
        ((float4*)s_ctx)[tid + i * 256] =
            ((const float4*)g_ctx)[(size_t)bh * 4096 + tid + i * 256];
    {
        size_t b4 = ((size_t)bh * NTOK + row_base) * 64;
#pragma unroll
        for (int i = 0; i < 8; i++)
            ((float4*)s_qp)[tid + i * 256] = ((const float4*)g_qp)[b4 + tid + i * 256];
    }
    if (tid < 64) ((float4*)s_ks)[tid] = ((const float4*)g_ksum)[bh * 64 + tid];
    __syncthreads();

    const int row = tid >> 3, dg = tid & 7;
    const int d0 = dg * 8;
    float acc[8];
#pragma unroll
    for (int i = 0; i < 8; i++) acc[i] = 0.f;
    float dsum = 0.f;
    const float* qr = s_qp + row * 256;
#pragma unroll 4
    for (int f = 0; f < 256; f++) {
        float qv = qr[f];
        dsum += qv * s_ks[f];
        float4 c0 = *(const float4*)&s_ctx[f * 64 + d0];
        float4 c1 = *(const float4*)&s_ctx[f * 64 + d0 + 4];
        acc[0] += qv * c0.x; acc[1] += qv * c0.y; acc[2] += qv * c0.z; acc[3] += qv * c0.w;
        acc[4] += qv * c1.x; acc[5] += qv * c1.y; acc[6] += qv * c1.z; acc[7] += qv * c1.w;
    }
    float rinv = 1.0f / dsum;
    int b = bh >> 3, h = bh & 7;
    int n = row_base + row;
    float* dp = g_attn + ((size_t)b * NTOK + n) * 512 + h * 64 + d0;
    *(float4*)dp       = make_float4(acc[0]*rinv, acc[1]*rinv, acc[2]*rinv, acc[3]*rinv);
    *(float4*)(dp + 4) = make_float4(acc[4]*rinv, acc[5]*rinv, acc[6]*rinv, acc[7]*rinv);
}

// ---------------- Wo GEMM + bo + rel-pos bias ----------------
__global__ void __launch_bounds__(256) wo_gemm(const float* __restrict__ Wo,
                                               const float* __restrict__ bo,
                                               const float* __restrict__ btab) {
    __shared__ float As[16][132];
    __shared__ float Bs[16][64];
    const int col0 = blockIdx.x * 64;
    const int row0 = blockIdx.y * 128;
    const int tid = threadIdx.x;
    const int tm = tid >> 4, tn = tid & 15;
    const int a_m = tid >> 1, a_k = (tid & 1) << 3;
    const int b_k = tid >> 4, b_n = (tid & 15) << 2;
    float acc[8][4];
#pragma unroll
    for (int i = 0; i < 8; i++)
#pragma unroll
        for (int j = 0; j < 4; j++) acc[i][j] = 0.f;

    for (int k0 = 0; k0 < 512; k0 += 16) {
        const float* ap = g_attn + (size_t)(row0 + a_m) * 512 + k0 + a_k;
        float4 av0 = *(const float4*)ap;
        float4 av1 = *(const float4*)(ap + 4);
        As[a_k + 0][a_m] = av0.x; As[a_k + 1][a_m] = av0.y;
        As[a_k + 2][a_m] = av0.z; As[a_k + 3][a_m] = av0.w;
        As[a_k + 4][a_m] = av1.x; As[a_k + 5][a_m] = av1.y;
        As[a_k + 6][a_m] = av1.z; As[a_k + 7][a_m] = av1.w;
        *(float4*)&Bs[b_k][b_n] =
            *(const float4*)(Wo + (size_t)(k0 + b_k) * 256 + col0 + b_n);
        __syncthreads();
#pragma unroll
        for (int kk = 0; kk < 16; kk++) {
            float a[8], b[4];
            *(float4*)(a)     = *(const float4*)&As[kk][tm * 8];
            *(float4*)(a + 4) = *(const float4*)&As[kk][tm * 8 + 4];
            *(float4*)(b)     = *(const float4*)&Bs[kk][tn * 4];
#pragma unroll
            for (int i = 0; i < 8; i++)
#pragma unroll
                for (int j = 0; j < 4; j++) acc[i][j] += a[i] * b[j];
        }
        __syncthreads();
    }
    float4 bo4 = *(const float4*)(bo + col0 + tn * 4);
#pragma unroll
    for (int i = 0; i < 8; i++) {
        int r = row0 + tm * 8 + i;
        int n = r & (NTOK - 1);
        int ii = n >> 7, jc = n & 127;
        int rel = ii - jc;
        rel = rel < -7 ? -7 : (rel > 7 ? 7 : rel);
        float bias = btab[rel + 7];
        float4 v = make_float4(acc[i][0] + bo4.x + bias, acc[i][1] + bo4.y + bias,
                               acc[i][2] + bo4.z + bias, acc[i][3] + bo4.w + bias);
        *(float4*)(g_y1 + (size_t)r * 256 + col0 + tn * 4) = v;
    }
}

// ---------------- Wp GEMM + bp -> out ----------------
__global__ void __launch_bounds__(256) wp_gemm(const float* __restrict__ Wp,
                                               const float* __restrict__ bp,
                                               float* __restrict__ out) {
    __shared__ float As[16][132];
    __shared__ float Bs[16][64];
    const int col0 = blockIdx.x * 64;
    const int row0 = blockIdx.y * 128;
    const int tid = threadIdx.x;
    const int tm = tid >> 4, tn = tid & 15;
    const int a_m = tid >> 1, a_k = (tid & 1) << 3;
    const int b_k = tid >> 4, b_n = (tid & 15) << 2;
    float acc[8][4];
#pragma unroll
    for (int i = 0; i < 8; i++)
#pragma unroll
        for (int j = 0; j < 4; j++) acc[i][j] = 0.f;

    for (int k0 = 0; k0 < 256; k0 += 16) {
        const float* ap = g_y1 + (size_t)(row0 + a_m) * 256 + k0 + a_k;
        float4 av0 = *(const float4*)ap;
        float4 av1 = *(const float4*)(ap + 4);
        As[a_k + 0][a_m] = av0.x; As[a_k + 1][a_m] = av0.y;
        As[a_k + 2][a_m] = av0.z; As[a_k + 3][a_m] = av0.w;
        As[a_k + 4][a_m] = av1.x; As[a_k + 5][a_m] = av1.y;
        As[a_k + 6][a_m] = av1.z; As[a_k + 7][a_m] = av1.w;
        *(float4*)&Bs[b_k][b_n] =
            *(const float4*)(Wp + (size_t)(k0 + b_k) * 256 + col0 + b_n);
        __syncthreads();
#pragma unroll
        for (int kk = 0; kk < 16; kk++) {
            float a[8], b[4];
            *(float4*)(a)     = *(const float4*)&As[kk][tm * 8];
            *(float4*)(a + 4) = *(const float4*)&As[kk][tm * 8 + 4];
            *(float4*)(b)     = *(const float4*)&Bs[kk][tn * 4];
#pragma unroll
            for (int i = 0; i < 8; i++)
#pragma unroll
                for (int j = 0; j < 4; j++) acc[i][j] += a[i] * b[j];
        }
        __syncthreads();
    }
    float4 bp4 = *(const float4*)(bp + col0 + tn * 4);
#pragma unroll
    for (int i = 0; i < 8; i++) {
        int r = row0 + tm * 8 + i;
        float4 v = make_float4(acc[i][0] + bp4.x, acc[i][1] + bp4.y,
                               acc[i][2] + bp4.z, acc[i][3] + bp4.w);
        *(float4*)(out + (size_t)r * 256 + col0 + tn * 4) = v;
    }
}

// ---------------- launch ----------------
extern "C" void kernel_launch(void* const* d_in, const int* in_sizes, int n_in,
                              void* d_out, int out_size) {
    (void)in_sizes; (void)n_in; (void)out_size;
    const float* x    = (const float*)d_in[0];
    const float* Wq   = (const float*)d_in[1];
    const float* Wk   = (const float*)d_in[2];
    const float* Wv   = (const float*)d_in[3];
    const float* Wo   = (const float*)d_in[4];
    const float* bo   = (const float*)d_in[5];
    const float* proj = (const float*)d_in[6];
    const float* Wp   = (const float*)d_in[7];
    const float* bp   = (const float*)d_in[8];
    const float* btab = (const float*)d_in[9];
    float* out = (float*)d_out;

    cudaFuncSetAttribute(phi_kernel, cudaFuncAttributeMaxDynamicSharedMemorySize, 73760);
    cudaFuncSetAttribute(attn_kernel, cudaFuncAttributeMaxDynamicSharedMemorySize, 99328);

    transpose_proj<<<64, 256>>>(proj);
    zero_accum<<<2081, 256>>>();
    qkv_gemm<<<dim3(8, 512, 3), 256>>>(x, Wq, Wk, Wv);
    phi_kernel<<<dim3(512, 32), 256, 73760>>>(1);   // query features
    phi_kernel<<<dim3(512, 32), 256, 73760>>>(0);   // key dd + partial max
    kmax_reduce<<<32, 256>>>();
    kp_finalize<<<dim3(512, 32), 256>>>();
    ctx_kernel<<<dim3(16, 32), 256>>>();
    attn_kernel<<<dim3(512, 32), 256, 99328>>>();
    wo_gemm<<<dim3(4, 512), 256>>>(Wo, bo, btab);
    wp_gemm<<<dim3(4, 512), 256>>>(Wp, bp, out);
}

// round 6
// speedup vs baseline: 1.1034x; 1.1034x over previous
#include <cuda_runtime.h>
#include <cuda_bf16.h>
#include <cstdint>
#include <cmath>

#define IMG 128
#define CH 256
#define NTOK 16384
#define NHEADS 8
#define DHE 64
#define NF 256
#define MTOT 65536
#define DN 0.3535533905932738f
#define RATIO 0.0625f
#define FEPS 1e-4f

// ---------------- device scratch (static, allocation-free) ----------------
__device__ float g_q[33554432];      // [32][16384][64]
__device__ float g_k[33554432];
__device__ float g_v[33554432];
__device__ float g_qp[134217728];    // [32][16384][256]
__device__ float g_kp[134217728];    // dd then kp in-place
__device__ float g_attn[33554432];   // [65536][512] head-concat
__device__ float g_projT[16384];     // [64][256]
__device__ float g_diag[524288];     // [32][16384]
__device__ float g_kmax_part[16384]; // [32][512]
__device__ float g_kmax[32];
__device__ float g_ksum[8192];       // [32][256]
__device__ float g_ctx[524288];      // [32][256][64]
__device__ float g_wT[393216];       // [3][512 n][256 k]  (W^T per matrix)
__device__ float g_wpT[65536];       // [256 n][256 c]
__device__ float g_wopT[131072];     // [256 n][512 k]  (Wo@Wp)^T
__device__ float g_b2[256];
__device__ float g_s[256];

// ================= bf16-split mma.sync GEMM =================
__device__ __forceinline__ uint32_t pk16(uint16_t a, uint16_t b) {
    return (uint32_t)a | ((uint32_t)b << 16);
}
__device__ __forceinline__ void spbf(float x, uint16_t& h, uint16_t& l) {
    __nv_bfloat16 hb = __float2bfloat16_rn(x);
    h = __bfloat16_as_ushort(hb);
    float r = x - __bfloat162float(hb);
    l = __bfloat16_as_ushort(__float2bfloat16_rn(r));
}
__device__ __forceinline__ void mma_bf16(float* c, const uint32_t* a, const uint32_t* b) {
    asm volatile(
        "mma.sync.aligned.m16n8k16.row.col.f32.bf16.bf16.f32 "
        "{%0,%1,%2,%3}, {%4,%5,%6,%7}, {%8,%9}, {%0,%1,%2,%3};"
        : "+f"(c[0]), "+f"(c[1]), "+f"(c[2]), "+f"(c[3])
        : "r"(a[0]), "r"(a[1]), "r"(a[2]), "r"(a[3]), "r"(b[0]), "r"(b[1]));
}

// C[128x128 tile] = A[MxK] @ BT[NxK]^T  with bf16 2-split, 3 products.
// qkv_mode=1: A = Aext (harness x), BT = g_wT[blockIdx.z], head-split store.
// qkv_mode=0: A = g_attn, BT = g_wopT, epilogue += b2 + bias(row)*s -> dout.
// NOTE: device scratch is referenced via device-side symbols ONLY (host-side
// symbol addresses are invalid kernel arguments).
#define LDB 20   // uint32 row stride (= 40 bf16, padded)
__global__ void __launch_bounds__(256) gemm_bf16x3(
    const float* __restrict__ Aext, int K, int qkv_mode,
    const float* __restrict__ btab, float* __restrict__ dout) {
    __shared__ __align__(16) uint32_t smem[4 * 2560];  // Ah, Al, Bh, Bl
    uint32_t* sAh = smem;
    uint32_t* sAl = smem + 2560;
    uint32_t* sBh = smem + 5120;
    uint32_t* sBl = smem + 7680;

    const int tid = threadIdx.x;
    const int wid = tid >> 5, lane = tid & 31;
    const int lr = lane >> 2;            // groupID 0..7
    const int kp = (lane & 3) * 2;       // tig*2: 0,2,4,6
    const int m0 = (wid & 3) * 32;
    const int n0 = (wid >> 2) * 64;
    const int row0 = blockIdx.y * 128;
    const int col0 = blockIdx.x * 128;

    const float* A;
    const float* BT;
    float* outb;
    if (qkv_mode) {
        A = Aext;
        BT = g_wT + (size_t)blockIdx.z * 131072;
        outb = blockIdx.z == 0 ? g_q : (blockIdx.z == 1 ? g_k : g_v);
    } else {
        A = g_attn;
        BT = g_wopT;
        outb = dout;
    }

    const int steps = K >> 5;
    const int lrow = tid >> 1;           // 0..127
    const int khalf = (tid & 1) * 16;    // 0 or 16
    const float* gA = A + (size_t)(row0 + lrow) * K + khalf;
    const float* gB = BT + (size_t)(col0 + lrow) * K + khalf;
    const int soff = lrow * LDB + (khalf >> 1);

    float c[2][8][4];
#pragma unroll
    for (int i = 0; i < 2; i++)
#pragma unroll
        for (int j = 0; j < 8; j++)
#pragma unroll
            for (int t = 0; t < 4; t++) c[i][j][t] = 0.f;

    float4 pa[4], pb[4];
#pragma unroll
    for (int g = 0; g < 4; g++) {
        pa[g] = *(const float4*)(gA + g * 4);
        pb[g] = *(const float4*)(gB + g * 4);
    }

    for (int st = 0; st < steps; st++) {
        __syncthreads();
        // split + store current chunk
#pragma unroll
        for (int g = 0; g < 4; g++) {
            uint16_t h0, h1, h2, h3, l0, l1, l2, l3;
            spbf(pa[g].x, h0, l0); spbf(pa[g].y, h1, l1);
            spbf(pa[g].z, h2, l2); spbf(pa[g].w, h3, l3);
            *(uint2*)(sAh + soff + g * 2) = make_uint2(pk16(h0, h1), pk16(h2, h3));
            *(uint2*)(sAl + soff + g * 2) = make_uint2(pk16(l0, l1), pk16(l2, l3));
            spbf(pb[g].x, h0, l0); spbf(pb[g].y, h1, l1);
            spbf(pb[g].z, h2, l2); spbf(pb[g].w, h3, l3);
            *(uint2*)(sBh + soff + g * 2) = make_uint2(pk16(h0, h1), pk16(h2, h3));
            *(uint2*)(sBl + soff + g * 2) = make_uint2(pk16(l0, l1), pk16(l2, l3));
        }
        __syncthreads();
        // prefetch next chunk
        if (st + 1 < steps) {
            const float* nA = gA + (st + 1) * 32;
            const float* nB = gB + (st + 1) * 32;
#pragma unroll
            for (int g = 0; g < 4; g++) {
                pa[g] = *(const float4*)(nA + g * 4);
                pb[g] = *(const float4*)(nB + g * 4);
            }
        }
        // compute on current chunk (32 k = 2 k16 steps)
#pragma unroll
        for (int ks = 0; ks < 2; ks++) {
            const int kb = ks * 8 + (kp >> 1);   // uint32 k offset
            uint32_t ah[2][4], al[2][4];
#pragma unroll
            for (int i = 0; i < 2; i++) {
                int i00 = (m0 + i * 16 + lr) * LDB + kb;
                ah[i][0] = sAh[i00];            ah[i][1] = sAh[i00 + 8 * LDB];
                ah[i][2] = sAh[i00 + 4];        ah[i][3] = sAh[i00 + 8 * LDB + 4];
                al[i][0] = sAl[i00];            al[i][1] = sAl[i00 + 8 * LDB];
                al[i][2] = sAl[i00 + 4];        al[i][3] = sAl[i00 + 8 * LDB + 4];
            }
#pragma unroll
            for (int j = 0; j < 8; j++) {
                int nb = (n0 + j * 8 + lr) * LDB + kb;
                uint32_t bh[2] = { sBh[nb], sBh[nb + 4] };
                uint32_t bl[2] = { sBl[nb], sBl[nb + 4] };
                mma_bf16(c[0][j], ah[0], bh);
                mma_bf16(c[1][j], ah[1], bh);
                mma_bf16(c[0][j], ah[0], bl);
                mma_bf16(c[1][j], ah[1], bl);
                mma_bf16(c[0][j], al[0], bh);
                mma_bf16(c[1][j], al[1], bh);
            }
        }
    }

    // ---------------- epilogue ----------------
#pragma unroll
    for (int i = 0; i < 2; i++) {
        const int rg0 = row0 + m0 + i * 16 + lr;
#pragma unroll
        for (int rr = 0; rr < 2; rr++) {
            const int r = rg0 + rr * 8;
            if (qkv_mode) {
                const int b = r >> 14, n = r & (NTOK - 1);
#pragma unroll
                for (int j = 0; j < 8; j++) {
                    const int cg = col0 + n0 + j * 8 + kp;
                    const int h = cg >> 6, off = cg & 63;
                    float* dp = outb + ((size_t)(b * 8 + h) * NTOK + n) * 64 + off;
                    *(float2*)dp = make_float2(c[i][j][rr * 2], c[i][j][rr * 2 + 1]);
                }
            } else {
                const int n = r & (NTOK - 1);
                const int ii = n >> 7, jc = n & 127;
                int rel = ii - jc;
                rel = rel < -7 ? -7 : (rel > 7 ? 7 : rel);
                const float brow = btab[rel + 7];
#pragma unroll
                for (int j = 0; j < 8; j++) {
                    const int cg = col0 + n0 + j * 8 + kp;
                    float2 b2v = *(const float2*)(g_b2 + cg);
                    float2 sv  = *(const float2*)(g_s + cg);
                    float* dp = outb + (size_t)r * 256 + cg;
                    *(float2*)dp = make_float2(c[i][j][rr * 2]     + b2v.x + brow * sv.x,
                                               c[i][j][rr * 2 + 1] + b2v.y + brow * sv.y);
                }
            }
        }
    }
}

// ---------------- tiny prep kernels ----------------
__global__ void transpose_proj(const float* __restrict__ proj) {
    int idx = blockIdx.x * 256 + threadIdx.x;
    if (idx < 16384) {
        int f = idx >> 6, d = idx & 63;
        g_projT[d * 256 + f] = proj[idx];
    }
}

__global__ void zero_accum() {
    int idx = blockIdx.x * 256 + threadIdx.x;
    if (idx < 524288) g_ctx[idx] = 0.f;
    else if (idx < 524288 + 8192) g_ksum[idx - 524288] = 0.f;
}

__global__ void wt_kernel(const float* __restrict__ Wq, const float* __restrict__ Wk,
                          const float* __restrict__ Wv) {
    int idx = blockIdx.x * 256 + threadIdx.x;   // 3*512*256
    int z = idx >> 17;
    int rem = idx & 131071;
    int n = rem >> 8, k = rem & 255;
    const float* W = z == 0 ? Wq : (z == 1 ? Wk : Wv);
    g_wT[idx] = W[(size_t)k * 512 + n];
}

__global__ void wpT_kernel(const float* __restrict__ Wp) {
    int idx = blockIdx.x * 256 + threadIdx.x;   // 256*256
    int n = idx >> 8, c = idx & 255;
    g_wpT[idx] = Wp[c * 256 + n];
}

// g_wopT[n][k] = sum_c Wo[k][c] * Wp[c][n]
__global__ void wowp_kernel(const float* __restrict__ Wo) {
    __shared__ float swo[256];
    int k = blockIdx.x, n = threadIdx.x;
    swo[n] = Wo[(size_t)k * 256 + n];
    __syncthreads();
    float acc = 0.f;
    const float* wp = g_wpT + n * 256;
#pragma unroll 4
    for (int c = 0; c < 256; c += 4) {
        float4 a = *(const float4*)(swo + c);
        float4 b = *(const float4*)(wp + c);
        acc += a.x * b.x + a.y * b.y + a.z * b.z + a.w * b.w;
    }
    g_wopT[n * 512 + k] = acc;
}

__global__ void b2s_kernel(const float* __restrict__ bo, const float* __restrict__ bp) {
    int n = threadIdx.x;
    float a = 0.f, ssum = 0.f;
    const float* wp = g_wpT + n * 256;
    for (int c = 0; c < 256; c++) {
        float w = wp[c];
        a += bo[c] * w;
        ssum += w;
    }
    g_b2[n] = a + bp[n];
    g_s[n] = ssum;
}

// ---------------- phi: dd = (q*dn) @ projT, + softmax-kernel epilogue ----------------
__global__ void __launch_bounds__(256) phi_kernel(int is_query) {
    extern __shared__ float sm[];
    float* s_projT = sm;               // 64*256
    float* s_q     = sm + 16384;       // 32*64
    float* s_red   = sm + 18432;       // 8
    const int tid = threadIdx.x;
    const int bh = blockIdx.y;
    const int row_base = blockIdx.x * 32;
    const float* src = is_query ? g_q : g_k;
    float* dst = is_query ? g_qp : g_kp;

#pragma unroll
    for (int i = 0; i < 16; i++)
        ((float4*)s_projT)[tid + i * 256] = ((const float4*)g_projT)[tid + i * 256];
    {
        const float4* qb = (const float4*)(src + ((size_t)bh * NTOK + row_base) * 64);
#pragma unroll
        for (int i = 0; i < 2; i++) {
            float4 v = qb[tid + i * 256];
            v.x *= DN; v.y *= DN; v.z *= DN; v.w *= DN;
            ((float4*)s_q)[tid + i * 256] = v;
        }
    }
    __syncthreads();

    const int tm = tid >> 4, tn = tid & 15;
    float acc0[16], acc1[16];
#pragma unroll
    for (int i = 0; i < 16; i++) { acc0[i] = 0.f; acc1[i] = 0.f; }
    float dg0 = 0.f, dg1 = 0.f;
    const float* q0 = s_q + (2 * tm) * 64;
    const float* q1 = q0 + 64;
#pragma unroll 4
    for (int d = 0; d < 64; d++) {
        float a0 = q0[d], a1 = q1[d];
        dg0 += a0 * a0; dg1 += a1 * a1;
#pragma unroll
        for (int jb = 0; jb < 4; jb++) {
            float4 p = *(const float4*)&s_projT[d * 256 + jb * 64 + tn * 4];
            acc0[jb*4+0] += a0 * p.x; acc0[jb*4+1] += a0 * p.y;
            acc0[jb*4+2] += a0 * p.z; acc0[jb*4+3] += a0 * p.w;
            acc1[jb*4+0] += a1 * p.x; acc1[jb*4+1] += a1 * p.y;
            acc1[jb*4+2] += a1 * p.z; acc1[jb*4+3] += a1 * p.w;
        }
    }
    float diag0 = 0.5f * dg0, diag1 = 0.5f * dg1;
    size_t base0 = ((size_t)bh * NTOK + row_base + 2 * tm) * 256;
    size_t base1 = base0 + 256;

    if (is_query) {
        float m0 = -1e30f, m1 = -1e30f;
#pragma unroll
        for (int i = 0; i < 16; i++) { m0 = fmaxf(m0, acc0[i]); m1 = fmaxf(m1, acc1[i]); }
#pragma unroll
        for (int o = 1; o < 16; o <<= 1) {
            m0 = fmaxf(m0, __shfl_xor_sync(0xffffffffu, m0, o));
            m1 = fmaxf(m1, __shfl_xor_sync(0xffffffffu, m1, o));
        }
#pragma unroll
        for (int jb = 0; jb < 4; jb++) {
            float4 o0, o1;
            o0.x = RATIO * (expf(acc0[jb*4+0] - diag0 - m0) + FEPS);
            o0.y = RATIO * (expf(acc0[jb*4+1] - diag0 - m0) + FEPS);
            o0.z = RATIO * (expf(acc0[jb*4+2] - diag0 - m0) + FEPS);
            o0.w = RATIO * (expf(acc0[jb*4+3] - diag0 - m0) + FEPS);
            o1.x = RATIO * (expf(acc1[jb*4+0] - diag1 - m1) + FEPS);
            o1.y = RATIO * (expf(acc1[jb*4+1] - diag1 - m1) + FEPS);
            o1.z = RATIO * (expf(acc1[jb*4+2] - diag1 - m1) + FEPS);
            o1.w = RATIO * (expf(acc1[jb*4+3] - diag1 - m1) + FEPS);
            *(float4*)(dst + base0 + jb * 64 + tn * 4) = o0;
            *(float4*)(dst + base1 + jb * 64 + tn * 4) = o1;
        }
    } else {
#pragma unroll
        for (int jb = 0; jb < 4; jb++) {
            *(float4*)(dst + base0 + jb * 64 + tn * 4) =
                make_float4(acc0[jb*4+0], acc0[jb*4+1], acc0[jb*4+2], acc0[jb*4+3]);
            *(float4*)(dst + base1 + jb * 64 + tn * 4) =
                make_float4(acc1[jb*4+0], acc1[jb*4+1], acc1[jb*4+2], acc1[jb*4+3]);
        }
        float bm = -1e30f;
#pragma unroll
        for (int i = 0; i < 16; i++) { bm = fmaxf(bm, acc0[i]); bm = fmaxf(bm, acc1[i]); }
#pragma unroll
        for (int o = 1; o < 32; o <<= 1) bm = fmaxf(bm, __shfl_xor_sync(0xffffffffu, bm, o));
        if ((tid & 31) == 0) s_red[tid >> 5] = bm;
        __syncthreads();
        if (tid == 0) {
            float m = s_red[0];
#pragma unroll
            for (int w = 1; w < 8; w++) m = fmaxf(m, s_red[w]);
            g_kmax_part[bh * 512 + blockIdx.x] = m;
        }
        if (tn == 0) {
            g_diag[(size_t)bh * NTOK + row_base + 2 * tm] = diag0;
            g_diag[(size_t)bh * NTOK + row_base + 2 * tm + 1] = diag1;
        }
    }
}

__global__ void kmax_reduce() {
    __shared__ float s[8];
    int bh = blockIdx.x, tid = threadIdx.x;
    float v = fmaxf(g_kmax_part[bh * 512 + tid], g_kmax_part[bh * 512 + 256 + tid]);
#pragma unroll
    for (int o = 1; o < 32; o <<= 1) v = fmaxf(v, __shfl_xor_sync(0xffffffffu, v, o));
    if ((tid & 31) == 0) s[tid >> 5] = v;
    __syncthreads();
    if (tid == 0) {
        float m = s[0];
#pragma unroll
        for (int w = 1; w < 8; w++) m = fmaxf(m, s[w]);
        g_kmax[bh] = m;
    }
}

__global__ void __launch_bounds__(256) kp_finalize() {
    const int bh = blockIdx.y, chunk = blockIdx.x, tid = threadIdx.x;
    const float m = g_kmax[bh];
    float lsum = 0.f;
    size_t rb = (size_t)bh * NTOK + chunk * 32;
#pragma unroll 4
    for (int r = 0; r < 32; r++) {
        float dia = g_diag[rb + r];
        size_t idx = (rb + r) * 256 + tid;
        float dd = g_kp[idx];
        float kp = RATIO * (expf(dd - dia - m) + FEPS);
        g_kp[idx] = kp;
        lsum += kp;
    }
    atomicAdd(&g_ksum[bh * 256 + tid], lsum);
}

// ---------------- context[bh][f][d] = sum_n kp[n][f] * v[n][d] ----------------
__global__ void __launch_bounds__(256) ctx_kernel() {
    __shared__ float s_kp[16 * 256];
    __shared__ float s_v[16 * 68];
    const int tid = threadIdx.x;
    const int bh = blockIdx.y;
    const int chunk = blockIdx.x;
    const int fb = tid >> 4, db = tid & 15;
    const int f0 = fb * 16, d0 = db * 4;
    float acc[16][4];
#pragma unroll
    for (int i = 0; i < 16; i++)
#pragma unroll
        for (int j = 0; j < 4; j++) acc[i][j] = 0.f;

    const float4* kp4 = (const float4*)g_kp;
    const float4* v4 = (const float4*)g_v;
    for (int t = 0; t < 64; t++) {
        size_t gr = (size_t)bh * NTOK + chunk * 1024 + t * 16;
#pragma unroll
        for (int i = 0; i < 4; i++) {
            int u = tid + i * 256;
            ((float4*)s_kp)[u] = kp4[(gr + (u >> 6)) * 64 + (u & 63)];
        }
        {
            int u = tid;
            *(float4*)&s_v[(u >> 4) * 68 + (u & 15) * 4] = v4[(gr + (u >> 4)) * 16 + (u & 15)];
        }
        __syncthreads();
#pragma unroll
        for (int nn = 0; nn < 16; nn++) {
            float4 vv = *(const float4*)&s_v[nn * 68 + d0];
#pragma unroll
            for (int i4 = 0; i4 < 4; i4++) {
                float4 pp = *(const float4*)&s_kp[nn * 256 + f0 + i4 * 4];
                float pv[4] = {pp.x, pp.y, pp.z, pp.w};
#pragma unroll
                for (int ii = 0; ii < 4; ii++) {
                    acc[i4*4+ii][0] += pv[ii] * vv.x;
                    acc[i4*4+ii][1] += pv[ii] * vv.y;
                    acc[i4*4+ii][2] += pv[ii] * vv.z;
                    acc[i4*4+ii][3] += pv[ii] * vv.w;
                }
            }
        }
        __syncthreads();
    }
#pragma unroll
    for (int i = 0; i < 16; i++)
#pragma unroll
        for (int j = 0; j < 4; j++)
            atomicAdd(&g_ctx[((size_t)bh * 256 + f0 + i) * 64 + d0 + j], acc[i][j]);
}

// ---------------- attn = (qp @ ctx) * d_inv ----------------
__global__ void __launch_bounds__(256) attn_kernel() {
    extern __shared__ float sm[];
    float* s_ctx = sm;            // 256*64
    float* s_qp  = sm + 16384;    // 32*256
    float* s_ks  = sm + 24576;    // 256
    const int tid = threadIdx.x;
    const int bh = blockIdx.y;
    const int row_base = blockIdx.x * 32;

#pragma unroll
    for (int i = 0; i < 16; i++)
        ((float4*)s_ctx)[tid + i * 256] =
            ((const float4*)g_ctx)[(size_t)bh * 4096 + tid + i * 256];
    {
        size_t b4 = ((size_t)bh * NTOK + row_base) * 64;
#pragma unroll
        for (int i = 0; i < 8; i++)
            ((float4*)s_qp)[tid + i * 256] = ((const float4*)g_qp)[b4 + tid + i * 256];
    }
    if (tid < 64) ((float4*)s_ks)[tid] = ((const float4*)g_ksum)[bh * 64 + tid];
    __syncthreads();

    const int row = tid >> 3, dg = tid & 7;
    const int d0 = dg * 8;
    float acc[8];
#pragma unroll
    for (int i = 0; i < 8; i++) acc[i] = 0.f;
    float dsum = 0.f;
    const float* qr = s_qp + row * 256;
#pragma unroll 4
    for (int f = 0; f < 256; f++) {
        float qv = qr[f];
        dsum += qv * s_ks[f];
        float4 c0 = *(const float4*)&s_ctx[f * 64 + d0];
        float4 c1 = *(const float4*)&s_ctx[f * 64 + d0 + 4];
        acc[0] += qv * c0.x; acc[1] += qv * c0.y; acc[2] += qv * c0.z; acc[3] += qv * c0.w;
        acc[4] += qv * c1.x; acc[5] += qv * c1.y; acc[6] += qv * c1.z; acc[7] += qv * c1.w;
    }
    float rinv = 1.0f / dsum;
    int b = bh >> 3, h = bh & 7;
    int n = row_base + row;
    float* dp = g_attn + ((size_t)b * NTOK + n) * 512 + h * 64 + d0;
    *(float4*)dp       = make_float4(acc[0]*rinv, acc[1]*rinv, acc[2]*rinv, acc[3]*rinv);
    *(float4*)(dp + 4) = make_float4(acc[4]*rinv, acc[5]*rinv, acc[6]*rinv, acc[7]*rinv);
}

// ---------------- launch ----------------
extern "C" void kernel_launch(void* const* d_in, const int* in_sizes, int n_in,
                              void* d_out, int out_size) {
    (void)in_sizes; (void)n_in; (void)out_size;
    const float* x    = (const float*)d_in[0];
    const float* Wq   = (const float*)d_in[1];
    const float* Wk   = (const float*)d_in[2];
    const float* Wv   = (const float*)d_in[3];
    const float* Wo   = (const float*)d_in[4];
    const float* bo   = (const float*)d_in[5];
    const float* proj = (const float*)d_in[6];
    const float* Wp   = (const float*)d_in[7];
    const float* bp   = (const float*)d_in[8];
    const float* btab = (const float*)d_in[9];
    float* out = (float*)d_out;

    cudaFuncSetAttribute(phi_kernel, cudaFuncAttributeMaxDynamicSharedMemorySize, 73760);
    cudaFuncSetAttribute(attn_kernel, cudaFuncAttributeMaxDynamicSharedMemorySize, 99328);

    transpose_proj<<<64, 256>>>(proj);
    zero_accum<<<2081, 256>>>();
    wt_kernel<<<1536, 256>>>(Wq, Wk, Wv);
    wpT_kernel<<<256, 256>>>(Wp);
    wowp_kernel<<<512, 256>>>(Wo);
    b2s_kernel<<<1, 256>>>(bo, bp);

    // QKV: A=x [65536x256], BT=g_wT[z] [512x256] (selected in-kernel)
    gemm_bf16x3<<<dim3(4, 512, 3), 256>>>(x, 256, 1, nullptr, nullptr);

    phi_kernel<<<dim3(512, 32), 256, 73760>>>(1);
    phi_kernel<<<dim3(512, 32), 256, 73760>>>(0);
    kmax_reduce<<<32, 256>>>();
    kp_finalize<<<dim3(512, 32), 256>>>();
    ctx_kernel<<<dim3(16, 32), 256>>>();
    attn_kernel<<<dim3(512, 32), 256, 99328>>>();

    // Final: A=g_attn [65536x512], BT=g_wopT [256x512] (in-kernel), fused bias
    gemm_bf16x3<<<dim3(2, 512, 1), 256>>>(nullptr, 512, 0, btab, out);
}

// round 8
// speedup vs baseline: 1.7660x; 1.6005x over previous
#include <cuda_runtime.h>
#include <cuda_bf16.h>
#include <cstdint>
#include <cmath>

#define NTOK 16384
#define DN 0.3535533905932738f
#define RATIO 0.0625f
#define FEPS 1e-4f

// ---------------- device scratch ----------------
__device__ float g_q[33554432];        // [32][16384][64]
__device__ float g_k[33554432];
__device__ float g_v[33554432];
__device__ float g_dd[134217728];      // [32][16384][256] raw key dd
__device__ uint32_t g_qph[67108864];   // qp bf16-hi [32][16384][256]
__device__ uint32_t g_qpl[67108864];   // qp bf16-lo
__device__ uint32_t g_kpTh[67108864];  // kpT bf16-hi [32][256][16384]
__device__ uint32_t g_kpTl[67108864];  // kpT bf16-lo
__device__ float g_attn[33554432];     // [65536][512]
__device__ float g_diag[524288];       // [32][16384]
__device__ float g_kmax_part[16384];
__device__ float g_kmax[32];
__device__ float g_ksum[8192];         // [32][256]
__device__ float g_ctx[524288];        // [32][256][64]
__device__ uint32_t g_ctxTh[262144];   // ctxT bf16-hi [32][64][256]
__device__ uint32_t g_ctxTl[262144];   // ctxT bf16-lo
__device__ float g_wT[393216];         // [3][512][256]
__device__ float g_wpT[65536];
__device__ float g_wopT[131072];       // [256][512]
__device__ float g_b2[256];
__device__ float g_s[256];

// ================= helpers =================
__device__ __forceinline__ uint32_t pk16(uint16_t a, uint16_t b) {
    return (uint32_t)a | ((uint32_t)b << 16);
}
__device__ __forceinline__ void spbf(float x, uint16_t& h, uint16_t& l) {
    __nv_bfloat16 hb = __float2bfloat16_rn(x);
    h = __bfloat16_as_ushort(hb);
    l = __bfloat16_as_ushort(__float2bfloat16_rn(x - __bfloat162float(hb)));
}
__device__ __forceinline__ uint16_t bf16of(float x) {
    return __bfloat16_as_ushort(__float2bfloat16_rn(x));
}
__device__ __forceinline__ float fbf16(uint16_t u) {
    return __bfloat162float(__ushort_as_bfloat16(u));
}
__device__ __forceinline__ void mma_bf16(float* c, const uint32_t* a, const uint32_t* b) {
    asm volatile(
        "mma.sync.aligned.m16n8k16.row.col.f32.bf16.bf16.f32 "
        "{%0,%1,%2,%3}, {%4,%5,%6,%7}, {%8,%9}, {%0,%1,%2,%3};"
        : "+f"(c[0]), "+f"(c[1]), "+f"(c[2]), "+f"(c[3])
        : "r"(a[0]), "r"(a[1]), "r"(a[2]), "r"(a[3]), "r"(b[0]), "r"(b[1]));
}

// ============= split-3 bf16 GEMM (verified) =============
#define LDB 20
__global__ void __launch_bounds__(256) gemm_bf16x3(
    const float* __restrict__ Aext, int K, int qkv_mode,
    const float* __restrict__ btab, float* __restrict__ dout) {
    __shared__ __align__(16) uint32_t smem[4 * 2560];
    uint32_t* sAh = smem;
    uint32_t* sAl = smem + 2560;
    uint32_t* sBh = smem + 5120;
    uint32_t* sBl = smem + 7680;

    const int tid = threadIdx.x;
    const int wid = tid >> 5, lane = tid & 31;
    const int lr = lane >> 2;
    const int kq = (lane & 3) * 2;
    const int m0 = (wid & 3) * 32;
    const int n0 = (wid >> 2) * 64;
    const int row0 = blockIdx.y * 128;
    const int col0 = blockIdx.x * 128;

    const float* A;
    const float* BT;
    float* outb;
    if (qkv_mode) {
        A = Aext;
        BT = g_wT + (size_t)blockIdx.z * 131072;
        outb = blockIdx.z == 0 ? g_q : (blockIdx.z == 1 ? g_k : g_v);
    } else {
        A = g_attn;
        BT = g_wopT;
        outb = dout;
    }

    const int steps = K >> 5;
    const int lrow = tid >> 1;
    const int khalf = (tid & 1) * 16;
    const float* gA = A + (size_t)(row0 + lrow) * K + khalf;
    const float* gB = BT + (size_t)(col0 + lrow) * K + khalf;
    const int soff = lrow * LDB + (khalf >> 1);

    float c[2][8][4];
#pragma unroll
    for (int i = 0; i < 2; i++)
#pragma unroll
        for (int j = 0; j < 8; j++)
#pragma unroll
            for (int t = 0; t < 4; t++) c[i][j][t] = 0.f;

    float4 pa[4], pb[4];
#pragma unroll
    for (int g = 0; g < 4; g++) {
        pa[g] = *(const float4*)(gA + g * 4);
        pb[g] = *(const float4*)(gB + g * 4);
    }

    for (int st = 0; st < steps; st++) {
        __syncthreads();
#pragma unroll
        for (int g = 0; g < 4; g++) {
            uint16_t h0, h1, h2, h3, l0, l1, l2, l3;
            spbf(pa[g].x, h0, l0); spbf(pa[g].y, h1, l1);
            spbf(pa[g].z, h2, l2); spbf(pa[g].w, h3, l3);
            *(uint2*)(sAh + soff + g * 2) = make_uint2(pk16(h0, h1), pk16(h2, h3));
            *(uint2*)(sAl + soff + g * 2) = make_uint2(pk16(l0, l1), pk16(l2, l3));
            spbf(pb[g].x, h0, l0); spbf(pb[g].y, h1, l1);
            spbf(pb[g].z, h2, l2); spbf(pb[g].w, h3, l3);
            *(uint2*)(sBh + soff + g * 2) = make_uint2(pk16(h0, h1), pk16(h2, h3));
            *(uint2*)(sBl + soff + g * 2) = make_uint2(pk16(l0, l1), pk16(l2, l3));
        }
        __syncthreads();
        if (st + 1 < steps) {
            const float* nA = gA + (st + 1) * 32;
            const float* nB = gB + (st + 1) * 32;
#pragma unroll
            for (int g = 0; g < 4; g++) {
                pa[g] = *(const float4*)(nA + g * 4);
                pb[g] = *(const float4*)(nB + g * 4);
            }
        }
#pragma unroll
        for (int ks = 0; ks < 2; ks++) {
            const int kb = ks * 8 + (kq >> 1);
            uint32_t ah[2][4], al[2][4];
#pragma unroll
            for (int i = 0; i < 2; i++) {
                int i00 = (m0 + i * 16 + lr) * LDB + kb;
                ah[i][0] = sAh[i00];            ah[i][1] = sAh[i00 + 8 * LDB];
                ah[i][2] = sAh[i00 + 4];        ah[i][3] = sAh[i00 + 8 * LDB + 4];
                al[i][0] = sAl[i00];            al[i][1] = sAl[i00 + 8 * LDB];
                al[i][2] = sAl[i00 + 4];        al[i][3] = sAl[i00 + 8 * LDB + 4];
            }
#pragma unroll
            for (int j = 0; j < 8; j++) {
                int nb = (n0 + j * 8 + lr) * LDB + kb;
                uint32_t bh2[2] = { sBh[nb], sBh[nb + 4] };
                uint32_t bl2[2] = { sBl[nb], sBl[nb + 4] };
                mma_bf16(c[0][j], ah[0], bh2);
                mma_bf16(c[1][j], ah[1], bh2);
                mma_bf16(c[0][j], ah[0], bl2);
                mma_bf16(c[1][j], ah[1], bl2);
                mma_bf16(c[0][j], al[0], bh2);
                mma_bf16(c[1][j], al[1], bh2);
            }
        }
    }

#pragma unroll
    for (int i = 0; i < 2; i++) {
        const int rg0 = row0 + m0 + i * 16 + lr;
#pragma unroll
        for (int rr = 0; rr < 2; rr++) {
            const int r = rg0 + rr * 8;
            if (qkv_mode) {
                const int b = r >> 14, n = r & (NTOK - 1);
#pragma unroll
                for (int j = 0; j < 8; j++) {
                    const int cg = col0 + n0 + j * 8 + kq;
                    const int h = cg >> 6, off = cg & 63;
                    float* dp = outb + ((size_t)(b * 8 + h) * NTOK + n) * 64 + off;
                    *(float2*)dp = make_float2(c[i][j][rr * 2], c[i][j][rr * 2 + 1]);
                }
            } else {
                const int n = r & (NTOK - 1);
                const int ii = n >> 7, jc = n & 127;
                int rel = ii - jc;
                rel = rel < -7 ? -7 : (rel > 7 ? 7 : rel);
                const float brow = btab[rel + 7];
#pragma unroll
                for (int j = 0; j < 8; j++) {
                    const int cg = col0 + n0 + j * 8 + kq;
                    float2 b2v = *(const float2*)(g_b2 + cg);
                    float2 sv  = *(const float2*)(g_s + cg);
                    float* dp = outb + (size_t)r * 256 + cg;
                    *(float2*)dp = make_float2(c[i][j][rr * 2]     + b2v.x + brow * sv.x,
                                               c[i][j][rr * 2 + 1] + b2v.y + brow * sv.y);
                }
            }
        }
    }
}

// ============= phi via mma (split-3): dd = (q*dn) @ proj^T =============
#define PLDA 36
__global__ void __launch_bounds__(256) phi_mma(const float* __restrict__ proj,
                                               int is_query) {
    extern __shared__ uint32_t sm[];
    uint32_t* sAh = sm;
    uint32_t* sAl = sAh + 128 * PLDA;
    uint32_t* sBh = sAl + 128 * PLDA;
    uint32_t* sBl = sBh + 256 * PLDA;
    float* s_diag = (float*)(sBl + 256 * PLDA);
    float* s_rmax = s_diag + 128;

    const int tid = threadIdx.x;
    const int wid = tid >> 5, lane = tid & 31;
    const int lr = lane >> 2, tig = lane & 3;
    const int m0 = (wid & 3) * 32;
    const int n0 = (wid >> 2) * 128;
    const int bh = blockIdx.y;
    const int row0 = blockIdx.x * 128;
    const float* src = is_query ? g_q : g_k;

#pragma unroll
    for (int i = 0; i < 16; i++) {
        int u = tid + i * 256;
        int f = u >> 4, c4 = u & 15;
        float4 v = ((const float4*)proj)[u];
        uint16_t h0, h1, h2, h3, l0, l1, l2, l3;
        spbf(v.x, h0, l0); spbf(v.y, h1, l1); spbf(v.z, h2, l2); spbf(v.w, h3, l3);
        sBh[f * PLDA + c4 * 2]     = pk16(h0, h1);
        sBh[f * PLDA + c4 * 2 + 1] = pk16(h2, h3);
        sBl[f * PLDA + c4 * 2]     = pk16(l0, l1);
        sBl[f * PLDA + c4 * 2 + 1] = pk16(l2, l3);
    }
#pragma unroll
    for (int i = 0; i < 8; i++) {
        int u = tid + i * 256;
        int r = u >> 4, c4 = u & 15;
        float4 v = *(const float4*)(src + ((size_t)bh * NTOK + row0 + r) * 64 + c4 * 4);
        v.x *= DN; v.y *= DN; v.z *= DN; v.w *= DN;
        uint16_t h0, h1, h2, h3, l0, l1, l2, l3;
        spbf(v.x, h0, l0); spbf(v.y, h1, l1); spbf(v.z, h2, l2); spbf(v.w, h3, l3);
        sAh[r * PLDA + c4 * 2]     = pk16(h0, h1);
        sAh[r * PLDA + c4 * 2 + 1] = pk16(h2, h3);
        sAl[r * PLDA + c4 * 2]     = pk16(l0, l1);
        sAl[r * PLDA + c4 * 2 + 1] = pk16(l2, l3);
        float ds = v.x * v.x + v.y * v.y + v.z * v.z + v.w * v.w;
#pragma unroll
        for (int o = 1; o < 16; o <<= 1) ds += __shfl_xor_sync(0xffffffffu, ds, o);
        if ((tid & 15) == 0) s_diag[r] = 0.5f * ds;
    }
    __syncthreads();

    float c[2][16][4];
#pragma unroll
    for (int i = 0; i < 2; i++)
#pragma unroll
        for (int j = 0; j < 16; j++)
#pragma unroll
            for (int t = 0; t < 4; t++) c[i][j][t] = 0.f;

#pragma unroll
    for (int ks = 0; ks < 4; ks++) {
        const int kb = ks * 8 + tig;
        uint32_t ah[2][4], al[2][4];
#pragma unroll
        for (int i = 0; i < 2; i++) {
            int b0 = (m0 + i * 16 + lr) * PLDA + kb;
            ah[i][0] = sAh[b0];             ah[i][1] = sAh[b0 + 8 * PLDA];
            ah[i][2] = sAh[b0 + 4];         ah[i][3] = sAh[b0 + 8 * PLDA + 4];
            al[i][0] = sAl[b0];             al[i][1] = sAl[b0 + 8 * PLDA];
            al[i][2] = sAl[b0 + 4];         al[i][3] = sAl[b0 + 8 * PLDA + 4];
        }
#pragma unroll
        for (int j = 0; j < 16; j++) {
            int nb = (n0 + j * 8 + lr) * PLDA + kb;
            uint32_t bh2[2] = { sBh[nb], sBh[nb + 4] };
            uint32_t bl2[2] = { sBl[nb], sBl[nb + 4] };
            mma_bf16(c[0][j], ah[0], bh2);
            mma_bf16(c[1][j], ah[1], bh2);
            mma_bf16(c[0][j], ah[0], bl2);
            mma_bf16(c[1][j], ah[1], bl2);
            mma_bf16(c[0][j], al[0], bh2);
            mma_bf16(c[1][j], al[1], bh2);
        }
    }

    if (is_query) {
#pragma unroll
        for (int i = 0; i < 2; i++)
#pragma unroll
            for (int rr = 0; rr < 2; rr++) {
                float mx = -1e30f;
#pragma unroll
                for (int j = 0; j < 16; j++) {
                    mx = fmaxf(mx, c[i][j][rr * 2]);
                    mx = fmaxf(mx, c[i][j][rr * 2 + 1]);
                }
                mx = fmaxf(mx, __shfl_xor_sync(0xffffffffu, mx, 1));
                mx = fmaxf(mx, __shfl_xor_sync(0xffffffffu, mx, 2));
                if (tig == 0)
                    s_rmax[(wid >> 2) * 128 + m0 + i * 16 + lr + rr * 8] = mx;
            }
        __syncthreads();
#pragma unroll
        for (int i = 0; i < 2; i++)
#pragma unroll
            for (int rr = 0; rr < 2; rr++) {
                const int r = m0 + i * 16 + lr + rr * 8;
                const float m = fmaxf(s_rmax[r], s_rmax[128 + r]);
                const float dia = s_diag[r];
                size_t base = ((size_t)bh * NTOK + row0 + r) * 128 + (n0 >> 1);
                uint32_t* dsth = g_qph + base;
                uint32_t* dstl = g_qpl + base;
#pragma unroll
                for (int j = 0; j < 16; j++) {
                    float v0 = RATIO * (expf(c[i][j][rr * 2]     - dia - m) + FEPS);
                    float v1 = RATIO * (expf(c[i][j][rr * 2 + 1] - dia - m) + FEPS);
                    uint16_t h0, l0, h1, l1;
                    spbf(v0, h0, l0); spbf(v1, h1, l1);
                    dsth[j * 4 + tig] = pk16(h0, h1);
                    dstl[j * 4 + tig] = pk16(l0, l1);
                }
            }
    } else {
        float bm = -1e30f;
#pragma unroll
        for (int i = 0; i < 2; i++)
#pragma unroll
            for (int j = 0; j < 16; j++)
#pragma unroll
                for (int t = 0; t < 4; t++) bm = fmaxf(bm, c[i][j][t]);
#pragma unroll
        for (int o = 16; o >= 1; o >>= 1) bm = fmaxf(bm, __shfl_xor_sync(0xffffffffu, bm, o));
        if (lane == 0) s_rmax[wid] = bm;
        __syncthreads();
        if (tid == 0) {
            float m = s_rmax[0];
#pragma unroll
            for (int w = 1; w < 8; w++) m = fmaxf(m, s_rmax[w]);
            g_kmax_part[bh * 512 + blockIdx.x] = m;
        }
        if (tid < 128) g_diag[(size_t)bh * NTOK + row0 + tid] = s_diag[tid];
#pragma unroll
        for (int i = 0; i < 2; i++)
#pragma unroll
            for (int rr = 0; rr < 2; rr++) {
                const int r = m0 + i * 16 + lr + rr * 8;
                float* dst = g_dd + ((size_t)bh * NTOK + row0 + r) * 256 + n0;
#pragma unroll
                for (int j = 0; j < 16; j++)
                    *(float2*)(dst + j * 8 + tig * 2) =
                        make_float2(c[i][j][rr * 2], c[i][j][rr * 2 + 1]);
            }
    }
}

__global__ void kmax_reduce() {
    __shared__ float s[8];
    int bh = blockIdx.x, tid = threadIdx.x;
    float v = (tid < 128) ? g_kmax_part[bh * 512 + tid] : -1e30f;
#pragma unroll
    for (int o = 1; o < 32; o <<= 1) v = fmaxf(v, __shfl_xor_sync(0xffffffffu, v, o));
    if ((tid & 31) == 0) s[tid >> 5] = v;
    __syncthreads();
    if (tid == 0) {
        float m = s[0];
#pragma unroll
        for (int w = 1; w < 8; w++) m = fmaxf(m, s[w]);
        g_kmax[bh] = m;
    }
}

// kp=ratio*(exp(dd-diag-m)+eps); write kpT hi/lo bf16 [bh][f][n]; accumulate ksum
__global__ void __launch_bounds__(256) kp_finalize_t() {
    extern __shared__ uint16_t skp[];   // hi [256][130], lo [256][130]
    uint16_t* skph = skp;
    uint16_t* skpl = skp + 256 * 130;
    const int tid = threadIdx.x;
    const int bh = blockIdx.y;
    const int row0 = blockIdx.x * 128;
    const float m = g_kmax[bh];
    const int f = tid;
    float ksum = 0.f;
    for (int g = 0; g < 128; g++) {
        float dia = g_diag[(size_t)bh * NTOK + row0 + g];
        float dd = g_dd[((size_t)bh * NTOK + row0 + g) * 256 + f];
        float kp = RATIO * (expf(dd - dia - m) + FEPS);
        ksum += kp;
        uint16_t h, l;
        spbf(kp, h, l);
        skph[f * 130 + g] = h;
        skpl[f * 130 + g] = l;
    }
    atomicAdd(&g_ksum[bh * 256 + f], ksum);
    __syncthreads();
    const int wid = tid >> 5, lane = tid & 31;
#pragma unroll 4
    for (int ff = 0; ff < 32; ff++) {
        int fr = wid * 32 + ff;
        const uint32_t* srh = (const uint32_t*)&skph[fr * 130];
        const uint32_t* srl = (const uint32_t*)&skpl[fr * 130];
        size_t base = ((size_t)bh * 256 + fr) * 8192 + (row0 >> 1);
        g_kpTh[base + lane] = srh[lane];
        g_kpTh[base + lane + 32] = srh[lane + 32];
        g_kpTl[base + lane] = srl[lane];
        g_kpTl[base + lane + 32] = srl[lane + 32];
    }
}

// ============= ctx via mma (split-3): C[f][d] += kpT @ vT^T =============
__global__ void __launch_bounds__(256) ctx_mma() {
    extern __shared__ uint32_t csm[];
    uint32_t* sAh = csm;                 // 256*20
    uint32_t* sAl = sAh + 5120;
    uint32_t* sBh = sAl + 5120;          // 64*20
    uint32_t* sBl = sBh + 1280;
    float* sv = (float*)(sBl + 1280);    // 32*68
    const int tid = threadIdx.x;
    const int wid = tid >> 5, lane = tid & 31;
    const int lr = lane >> 2, tig = lane & 3;
    const int m0 = (wid & 3) * 64;
    const int n0w = (wid >> 2) * 32;
    const int bh = blockIdx.y;
    const int kc = blockIdx.x;

    float c[4][4][4];
#pragma unroll
    for (int i = 0; i < 4; i++)
#pragma unroll
        for (int j = 0; j < 4; j++)
#pragma unroll
            for (int t = 0; t < 4; t++) c[i][j][t] = 0.f;

    for (int nc = 0; nc < 64; nc++) {
        const int nbase = kc * 2048 + nc * 32;
#pragma unroll
        for (int i = 0; i < 16; i++) {
            int u = tid + i * 256;
            int fr = u >> 4, cw = u & 15;
            size_t gi = ((size_t)bh * 256 + fr) * 8192 + (nbase >> 1) + cw;
            sAh[fr * 20 + cw] = g_kpTh[gi];
            sAl[fr * 20 + cw] = g_kpTl[gi];
        }
#pragma unroll
        for (int i = 0; i < 2; i++) {
            int u = tid + i * 256;
            int n = u >> 4, c4 = u & 15;
            *(float4*)&sv[n * 68 + c4 * 4] =
                *(const float4*)(g_v + ((size_t)bh * NTOK + nbase + n) * 64 + c4 * 4);
        }
        __syncthreads();
#pragma unroll
        for (int i = 0; i < 4; i++) {
            int u = tid + i * 256;
            int d = u >> 4, nw = u & 15;
            uint16_t h0, l0, h1, l1;
            spbf(sv[(nw * 2) * 68 + d], h0, l0);
            spbf(sv[(nw * 2 + 1) * 68 + d], h1, l1);
            sBh[d * 20 + nw] = pk16(h0, h1);
            sBl[d * 20 + nw] = pk16(l0, l1);
        }
        __syncthreads();
#pragma unroll
        for (int ks = 0; ks < 2; ks++) {
            const int kb = ks * 8 + tig;
            uint32_t ah[4][4], al[4][4];
#pragma unroll
            for (int i = 0; i < 4; i++) {
                int b0 = (m0 + i * 16 + lr) * 20 + kb;
                ah[i][0] = sAh[b0];       ah[i][1] = sAh[b0 + 160];
                ah[i][2] = sAh[b0 + 4];   ah[i][3] = sAh[b0 + 164];
                al[i][0] = sAl[b0];       al[i][1] = sAl[b0 + 160];
                al[i][2] = sAl[b0 + 4];   al[i][3] = sAl[b0 + 164];
            }
#pragma unroll
            for (int j = 0; j < 4; j++) {
                int nb = (n0w + j * 8 + lr) * 20 + kb;
                uint32_t bh2[2] = { sBh[nb], sBh[nb + 4] };
                uint32_t bl2[2] = { sBl[nb], sBl[nb + 4] };
#pragma unroll
                for (int i = 0; i < 4; i++) {
                    mma_bf16(c[i][j], ah[i], bh2);
                    mma_bf16(c[i][j], ah[i], bl2);
                    mma_bf16(c[i][j], al[i], bh2);
                }
            }
        }
        __syncthreads();
    }
#pragma unroll
    for (int i = 0; i < 4; i++)
#pragma unroll
        for (int j = 0; j < 4; j++)
#pragma unroll
            for (int rr = 0; rr < 2; rr++) {
                int fr = m0 + i * 16 + lr + rr * 8;
                int d = n0w + j * 8 + tig * 2;
                atomicAdd(&g_ctx[((size_t)bh * 256 + fr) * 64 + d], c[i][j][rr * 2]);
                atomicAdd(&g_ctx[((size_t)bh * 256 + fr) * 64 + d + 1], c[i][j][rr * 2 + 1]);
            }
}

__global__ void ctxT_kernel() {
    const int bh = blockIdx.x, tid = threadIdx.x;
    for (int i = 0; i < 64; i++) {
        int u = tid + i * 256;
        int f = u >> 6, d = u & 63;
        float v = g_ctx[((size_t)bh * 256 + f) * 64 + d];
        uint16_t h, l;
        spbf(v, h, l);
        size_t di = ((size_t)bh * 64 + d) * 256 + f;
        ((uint16_t*)g_ctxTh)[di] = h;
        ((uint16_t*)g_ctxTl)[di] = l;
    }
}

// ============= attn via mma (split-3) + fused d_inv =============
__global__ void __launch_bounds__(256) attn_mma() {
    __shared__ uint32_t sAh[128 * 20];
    __shared__ uint32_t sAl[128 * 20];
    __shared__ uint32_t sBh[64 * 20];
    __shared__ uint32_t sBl[64 * 20];
    __shared__ float sk[32];
    __shared__ float sdsum[128];
    const int tid = threadIdx.x;
    const int wid = tid >> 5, lane = tid & 31;
    const int lr = lane >> 2, tig = lane & 3;
    const int m0 = (wid & 3) * 32;
    const int n0w = (wid >> 2) * 32;
    const int bh = blockIdx.y;
    const int row0 = blockIdx.x * 128;

    float c[2][4][4];
#pragma unroll
    for (int i = 0; i < 2; i++)
#pragma unroll
        for (int j = 0; j < 4; j++)
#pragma unroll
            for (int t = 0; t < 4; t++) c[i][j][t] = 0.f;
    float dsum = 0.f;

    for (int fc = 0; fc < 8; fc++) {
#pragma unroll
        for (int i = 0; i < 8; i++) {
            int u = tid + i * 256;
            int n = u >> 4, cw = u & 15;
            size_t gi = ((size_t)bh * NTOK + row0 + n) * 128 + fc * 16 + cw;
            sAh[n * 20 + cw] = g_qph[gi];
            sAl[n * 20 + cw] = g_qpl[gi];
        }
#pragma unroll
        for (int i = 0; i < 4; i++) {
            int u = tid + i * 256;
            int d = u >> 4, cw = u & 15;
            size_t gi = ((size_t)bh * 64 + d) * 128 + fc * 16 + cw;
            sBh[d * 20 + cw] = g_ctxTh[gi];
            sBl[d * 20 + cw] = g_ctxTl[gi];
        }
        if (tid < 32) sk[tid] = g_ksum[bh * 256 + fc * 32 + tid];
        __syncthreads();
        if (tid < 128) {
#pragma unroll
            for (int w = 0; w < 16; w++) {
                uint32_t ph = sAh[tid * 20 + w];
                uint32_t pl = sAl[tid * 20 + w];
                dsum += (fbf16((uint16_t)(ph & 0xFFFF)) + fbf16((uint16_t)(pl & 0xFFFF))) * sk[w * 2]
                      + (fbf16((uint16_t)(ph >> 16)) + fbf16((uint16_t)(pl >> 16))) * sk[w * 2 + 1];
            }
        }
#pragma unroll
        for (int ks = 0; ks < 2; ks++) {
            const int kb = ks * 8 + tig;
            uint32_t ah[2][4], al[2][4];
#pragma unroll
            for (int i = 0; i < 2; i++) {
                int b0 = (m0 + i * 16 + lr) * 20 + kb;
                ah[i][0] = sAh[b0];       ah[i][1] = sAh[b0 + 160];
                ah[i][2] = sAh[b0 + 4];   ah[i][3] = sAh[b0 + 164];
                al[i][0] = sAl[b0];       al[i][1] = sAl[b0 + 160];
                al[i][2] = sAl[b0 + 4];   al[i][3] = sAl[b0 + 164];
            }
#pragma unroll
            for (int j = 0; j < 4; j++) {
                int nb = (n0w + j * 8 + lr) * 20 + kb;
                uint32_t bh2[2] = { sBh[nb], sBh[nb + 4] };
                uint32_t bl2[2] = { sBl[nb], sBl[nb + 4] };
#pragma unroll
                for (int i = 0; i < 2; i++) {
                    mma_bf16(c[i][j], ah[i], bh2);
                    mma_bf16(c[i][j], ah[i], bl2);
                    mma_bf16(c[i][j], al[i], bh2);
                }
            }
        }
        __syncthreads();
    }
    if (tid < 128) sdsum[tid] = dsum;
    __syncthreads();

    const int b = bh >> 3, h = bh & 7;
#pragma unroll
    for (int i = 0; i < 2; i++)
#pragma unroll
        for (int rr = 0; rr < 2; rr++) {
            const int r = m0 + i * 16 + lr + rr * 8;
            const float rinv = 1.0f / sdsum[r];
            const int n = row0 + r;
            float* dp = g_attn + ((size_t)b * NTOK + n) * 512 + h * 64 + n0w;
#pragma unroll
            for (int j = 0; j < 4; j++)
                *(float2*)(dp + j * 8 + tig * 2) =
                    make_float2(c[i][j][rr * 2] * rinv, c[i][j][rr * 2 + 1] * rinv);
        }
}

// ---------------- prep kernels ----------------
__global__ void zero_accum() {
    int idx = blockIdx.x * 256 + threadIdx.x;
    if (idx < 524288) g_ctx[idx] = 0.f;
    else if (idx < 524288 + 8192) g_ksum[idx - 524288] = 0.f;
}

__global__ void wt_kernel(const float* __restrict__ Wq, const float* __restrict__ Wk,
                          const float* __restrict__ Wv) {
    int idx = blockIdx.x * 256 + threadIdx.x;
    int z = idx >> 17;
    int rem = idx & 131071;
    int n = rem >> 8, k = rem & 255;
    const float* W = z == 0 ? Wq : (z == 1 ? Wk : Wv);
    g_wT[idx] = W[(size_t)k * 512 + n];
}

__global__ void wpT_kernel(const float* __restrict__ Wp) {
    int idx = blockIdx.x * 256 + threadIdx.x;
    int n = idx >> 8, c = idx & 255;
    g_wpT[idx] = Wp[c * 256 + n];
}

__global__ void wowp_kernel(const float* __restrict__ Wo) {
    __shared__ float swo[256];
    int k = blockIdx.x, n = threadIdx.x;
    swo[n] = Wo[(size_t)k * 256 + n];
    __syncthreads();
    float acc = 0.f;
    const float* wp = g_wpT + n * 256;
#pragma unroll 4
    for (int cc = 0; cc < 256; cc += 4) {
        float4 a = *(const float4*)(swo + cc);
        float4 bb = *(const float4*)(wp + cc);
        acc += a.x * bb.x + a.y * bb.y + a.z * bb.z + a.w * bb.w;
    }
    g_wopT[n * 512 + k] = acc;
}

__global__ void b2s_kernel(const float* __restrict__ bo, const float* __restrict__ bp) {
    int n = threadIdx.x;
    float a = 0.f, ssum = 0.f;
    const float* wp = g_wpT + n * 256;
    for (int cc = 0; cc < 256; cc++) {
        float w = wp[cc];
        a += bo[cc] * w;
        ssum += w;
    }
    g_b2[n] = a + bp[n];
    g_s[n] = ssum;
}

// ---------------- launch ----------------
extern "C" void kernel_launch(void* const* d_in, const int* in_sizes, int n_in,
                              void* d_out, int out_size) {
    (void)in_sizes; (void)n_in; (void)out_size;
    const float* x    = (const float*)d_in[0];
    const float* Wq   = (const float*)d_in[1];
    const float* Wk   = (const float*)d_in[2];
    const float* Wv   = (const float*)d_in[3];
    const float* Wo   = (const float*)d_in[4];
    const float* bo   = (const float*)d_in[5];
    const float* proj = (const float*)d_in[6];
    const float* Wp   = (const float*)d_in[7];
    const float* bp   = (const float*)d_in[8];
    const float* btab = (const float*)d_in[9];
    float* out = (float*)d_out;

    cudaFuncSetAttribute(phi_mma, cudaFuncAttributeMaxDynamicSharedMemorySize, 112128);
    cudaFuncSetAttribute(kp_finalize_t, cudaFuncAttributeMaxDynamicSharedMemorySize, 133120);
    cudaFuncSetAttribute(ctx_mma, cudaFuncAttributeMaxDynamicSharedMemorySize, 59904);

    zero_accum<<<2081, 256>>>();
    wt_kernel<<<1536, 256>>>(Wq, Wk, Wv);
    wpT_kernel<<<256, 256>>>(Wp);
    wowp_kernel<<<512, 256>>>(Wo);
    b2s_kernel<<<1, 256>>>(bo, bp);

    gemm_bf16x3<<<dim3(4, 512, 3), 256>>>(x, 256, 1, nullptr, nullptr);

    phi_mma<<<dim3(128, 32), 256, 112128>>>(proj, 1);
    phi_mma<<<dim3(128, 32), 256, 112128>>>(proj, 0);
    kmax_reduce<<<32, 256>>>();
    kp_finalize_t<<<dim3(128, 32), 256, 133120>>>();
    ctx_mma<<<dim3(8, 32), 256, 59904>>>();
    ctxT_kernel<<<32, 256>>>();
    attn_mma<<<dim3(128, 32), 256>>>();

    gemm_bf16x3<<<dim3(2, 512, 1), 256>>>(nullptr, 512, 0, btab, out);
}

// round 12
// speedup vs baseline: 2.0046x; 1.1351x over previous
#include <cuda_runtime.h>
#include <cuda_bf16.h>
#include <cstdint>
#include <cmath>

#define NTOK 16384
#define DN 0.3535533905932738f
#define RATIO 0.0625f
#define FEPS 1e-4f

// ---------------- device scratch ----------------
__device__ uint32_t g_xh[8388608], g_xl[8388608];          // x planes [65536][128]
__device__ uint32_t g_wTh[196608], g_wTl[196608];          // [3][512][128]
__device__ uint32_t g_wopTh[65536], g_wopTl[65536];        // [256][256]
__device__ uint32_t g_qh[16777216], g_ql[16777216];        // [32][16384][32]
__device__ uint32_t g_kh[16777216], g_kl[16777216];
__device__ uint32_t g_attnh[16777216], g_attnl[16777216];  // [65536][256]
__device__ float g_v[33554432];                            // [32][16384][64]
__device__ float g_dd[134217728];                          // [32][16384][256]
__device__ uint32_t g_qph[67108864], g_qpl[67108864];      // qp planes [32][16384][128]
__device__ uint32_t g_kpTh[67108864], g_kpTl[67108864];    // kpT planes [32][256][8192]
__device__ float g_diag[524288];
__device__ float g_kmax_part[16384];
__device__ float g_kmax[32];
__device__ float g_ksum[8192];
__device__ float g_ctx[524288];                            // [32][256][64]
__device__ uint32_t g_ctxTh[262144], g_ctxTl[262144];      // [32][64][128]
__device__ float g_wpT[65536];
__device__ float g_wopT[131072];
__device__ float g_b2[256];
__device__ float g_s[256];

// ================= helpers =================
__device__ __forceinline__ uint32_t pk16(uint16_t a, uint16_t b) {
    return (uint32_t)a | ((uint32_t)b << 16);
}
__device__ __forceinline__ void spbf(float x, uint16_t& h, uint16_t& l) {
    __nv_bfloat16 hb = __float2bfloat16_rn(x);
    h = __bfloat16_as_ushort(hb);
    l = __bfloat16_as_ushort(__float2bfloat16_rn(x - __bfloat162float(hb)));
}
__device__ __forceinline__ float fbf16(uint16_t u) {
    return __bfloat162float(__ushort_as_bfloat16(u));
}
__device__ __forceinline__ void mma_bf16(float* c, const uint32_t* a, const uint32_t* b) {
    asm volatile(
        "mma.sync.aligned.m16n8k16.row.col.f32.bf16.bf16.f32 "
        "{%0,%1,%2,%3}, {%4,%5,%6,%7}, {%8,%9}, {%0,%1,%2,%3};"
        : "+f"(c[0]), "+f"(c[1]), "+f"(c[2]), "+f"(c[3])
        : "r"(a[0]), "r"(a[1]), "r"(a[2]), "r"(a[3]), "r"(b[0]), "r"(b[1]));
}
__device__ __forceinline__ uint32_t s2u(const void* p) {
    return (uint32_t)__cvta_generic_to_shared(p);
}
__device__ __forceinline__ void ldm_x4(uint32_t* r, uint32_t addr) {
    asm volatile("ldmatrix.sync.aligned.m8n8.x4.shared.b16 {%0,%1,%2,%3}, [%4];"
        : "=r"(r[0]), "=r"(r[1]), "=r"(r[2]), "=r"(r[3]) : "r"(addr));
}
__device__ __forceinline__ void cpa16(uint32_t dst, const void* src) {
    asm volatile("cp.async.ca.shared.global [%0], [%1], 16;" :: "r"(dst), "l"(src));
}
__device__ __forceinline__ void cpa_commit() { asm volatile("cp.async.commit_group;"); }
template <int N> __device__ __forceinline__ void cpa_wait() {
    asm volatile("cp.async.wait_group %0;" :: "n"(N));
}

// ============= pre-split cp.async+ldmatrix GEMM =============
// C[128x128] = (Ah+Al) @ (Bh+Bl)^T  (split-3 products), planes pre-packed.
// qkv_mode=1: A=x planes, B=wT[z] planes; out: z<2 -> q/k planes, z=2 -> v fp32.
// qkv_mode=0: A=attn planes, B=wopT planes; out fp32 + fused bias.
#define GLD 20  // smem row stride (uint32)
__device__ __forceinline__ void gemm2_issue(
    const uint32_t* pA0, const uint32_t* pA1,
    const uint32_t* pB0, const uint32_t* pB1,
    int Ku, int row0, int col0, int st, int stage,
    uint32_t sbase, int tid) {
#pragma unroll
    for (int i = 0; i < 8; i++) {
        int u = tid + i * 256;         // 0..2047
        int pl = u >> 9;               // 0:Ah 1:Al 2:Bh 3:Bl
        int t = u & 511;
        int row = t >> 2, c4 = (t & 3) * 4;
        const uint32_t* src;
        if (pl == 0)      src = pA0 + (size_t)(row0 + row) * Ku + st * 16 + c4;
        else if (pl == 1) src = pA1 + (size_t)(row0 + row) * Ku + st * 16 + c4;
        else if (pl == 2) src = pB0 + (size_t)(col0 + row) * Ku + st * 16 + c4;
        else              src = pB1 + (size_t)(col0 + row) * Ku + st * 16 + c4;
        uint32_t dst = sbase + (uint32_t)(stage * 10240 + pl * 2560 + row * GLD + c4) * 4;
        cpa16(dst, src);
    }
    cpa_commit();
}

__global__ void __launch_bounds__(256) gemm2(
    int K, int qkv_mode, const float* __restrict__ btab, float* __restrict__ dout) {
    extern __shared__ uint32_t gsm[];
    const uint32_t sbase = s2u(gsm);
    const int tid = threadIdx.x;
    const int wid = tid >> 5, lane = tid & 31;
    const int lr = lane >> 2, tig = lane & 3;
    const int m0 = (wid & 3) * 32;
    const int n0 = (wid >> 2) * 64;
    const int row0 = blockIdx.y * 128;
    const int col0 = blockIdx.x * 128;

    const uint32_t *pA0, *pA1, *pB0, *pB1;
    if (qkv_mode) {
        pA0 = g_xh; pA1 = g_xl;
        pB0 = g_wTh + (size_t)blockIdx.z * 65536;
        pB1 = g_wTl + (size_t)blockIdx.z * 65536;
    } else {
        pA0 = g_attnh; pA1 = g_attnl;
        pB0 = g_wopTh; pB1 = g_wopTl;
    }
    const int Ku = K >> 1;
    const int steps = K >> 5;

    float c[2][8][4];
#pragma unroll
    for (int i = 0; i < 2; i++)
#pragma unroll
        for (int j = 0; j < 8; j++)
#pragma unroll
            for (int t = 0; t < 4; t++) c[i][j][t] = 0.f;

    gemm2_issue(pA0, pA1, pB0, pB1, Ku, row0, col0, 0, 0, sbase, tid);

    for (int st = 0; st < steps; st++) {
        if (st + 1 < steps) {
            gemm2_issue(pA0, pA1, pB0, pB1, Ku, row0, col0, st + 1, (st + 1) & 1, sbase, tid);
            cpa_wait<1>();
        } else {
            cpa_wait<0>();
        }
        __syncthreads();
        const uint32_t stoff = (uint32_t)((st & 1) * 10240) * 4;
        const uint32_t AhB = sbase + stoff;
        const uint32_t AlB = AhB + 2560 * 4;
        const uint32_t BhB = AhB + 5120 * 4;
        const uint32_t BlB = AhB + 7680 * 4;
#pragma unroll
        for (int ks = 0; ks < 2; ks++) {
            uint32_t ah[2][4], al[2][4];
#pragma unroll
            for (int i = 0; i < 2; i++) {
                uint32_t ro = (uint32_t)((m0 + i * 16 + (lane & 15)) * GLD) * 4
                              + ks * 32 + (lane >> 4) * 16;
                ldm_x4(ah[i], AhB + ro);
                ldm_x4(al[i], AlB + ro);
            }
#pragma unroll
            for (int jg = 0; jg < 4; jg++) {
                uint32_t ro = (uint32_t)((n0 + jg * 16 + (lane & 15)) * GLD) * 4
                              + ks * 32 + (lane >> 4) * 16;
                uint32_t bh4[4], bl4[4];
                ldm_x4(bh4, BhB + ro);
                ldm_x4(bl4, BlB + ro);
                uint32_t b0h[2] = { bh4[0], bh4[2] }, b1h[2] = { bh4[1], bh4[3] };
                uint32_t b0l[2] = { bl4[0], bl4[2] }, b1l[2] = { bl4[1], bl4[3] };
#pragma unroll
                for (int i = 0; i < 2; i++) {
                    mma_bf16(c[i][jg * 2],     ah[i], b0h);
                    mma_bf16(c[i][jg * 2],     ah[i], b0l);
                    mma_bf16(c[i][jg * 2],     al[i], b0h);
                    mma_bf16(c[i][jg * 2 + 1], ah[i], b1h);
                    mma_bf16(c[i][jg * 2 + 1], ah[i], b1l);
                    mma_bf16(c[i][jg * 2 + 1], al[i], b1h);
                }
            }
        }
        __syncthreads();
    }

    // ---------------- epilogue ----------------
#pragma unroll
    for (int i = 0; i < 2; i++) {
#pragma unroll
        for (int rr = 0; rr < 2; rr++) {
            const int r = row0 + m0 + i * 16 + lr + rr * 8;
            if (qkv_mode) {
                const int b = r >> 14, n = r & (NTOK - 1);
                const int z = blockIdx.z;
                if (z < 2) {
                    uint32_t* ph = z == 0 ? g_qh : g_kh;
                    uint32_t* pl = z == 0 ? g_ql : g_kl;
#pragma unroll
                    for (int j = 0; j < 8; j++) {
                        const int cg = col0 + n0 + j * 8 + tig * 2;
                        const int hh = cg >> 6, off = cg & 63;
                        size_t di = ((size_t)(b * 8 + hh) * NTOK + n) * 32 + (off >> 1);
                        uint16_t h0, l0, h1, l1;
                        spbf(c[i][j][rr * 2], h0, l0);
                        spbf(c[i][j][rr * 2 + 1], h1, l1);
                        ph[di] = pk16(h0, h1);
                        pl[di] = pk16(l0, l1);
                    }
                } else {
#pragma unroll
                    for (int j = 0; j < 8; j++) {
                        const int cg = col0 + n0 + j * 8 + tig * 2;
                        const int hh = cg >> 6, off = cg & 63;
                        float* dp = g_v + ((size_t)(b * 8 + hh) * NTOK + n) * 64 + off;
                        *(float2*)dp = make_float2(c[i][j][rr * 2], c[i][j][rr * 2 + 1]);
                    }
                }
            } else {
                const int n = r & (NTOK - 1);
                const int ii = n >> 7, jc = n & 127;
                int rel = ii - jc;
                rel = rel < -7 ? -7 : (rel > 7 ? 7 : rel);
                const float brow = btab[rel + 7];
#pragma unroll
                for (int j = 0; j < 8; j++) {
                    const int cg = col0 + n0 + j * 8 + tig * 2;
                    float2 b2v = *(const float2*)(g_b2 + cg);
                    float2 sv  = *(const float2*)(g_s + cg);
                    float* dp = dout + (size_t)r * 256 + cg;
                    *(float2*)dp = make_float2(c[i][j][rr * 2]     + b2v.x + brow * sv.x,
                                               c[i][j][rr * 2 + 1] + b2v.y + brow * sv.y);
                }
            }
        }
    }
}

// ============= phi via mma (split-3): dd = q @ (DN*proj)^T =============
#define PLDA 36
__global__ void __launch_bounds__(256) phi_mma(const float* __restrict__ proj,
                                               int is_query) {
    extern __shared__ uint32_t sm[];
    uint32_t* sAh = sm;
    uint32_t* sAl = sAh + 128 * PLDA;
    uint32_t* sBh = sAl + 128 * PLDA;
    uint32_t* sBl = sBh + 256 * PLDA;
    float* s_diag = (float*)(sBl + 256 * PLDA);
    float* s_rmax = s_diag + 128;

    const int tid = threadIdx.x;
    const int wid = tid >> 5, lane = tid & 31;
    const int lr = lane >> 2, tig = lane & 3;
    const int m0 = (wid & 3) * 32;
    const int n0 = (wid >> 2) * 128;
    const int bh = blockIdx.y;
    const int row0 = blockIdx.x * 128;
    const uint32_t* ph = is_query ? g_qh : g_kh;
    const uint32_t* pl = is_query ? g_ql : g_kl;

    // B = proj*DN [256][64], split planes
#pragma unroll
    for (int i = 0; i < 16; i++) {
        int u = tid + i * 256;
        int f = u >> 4, c4 = u & 15;
        float4 v = ((const float4*)proj)[u];
        v.x *= DN; v.y *= DN; v.z *= DN; v.w *= DN;
        uint16_t h0, h1, h2, h3, l0, l1, l2, l3;
        spbf(v.x, h0, l0); spbf(v.y, h1, l1); spbf(v.z, h2, l2); spbf(v.w, h3, l3);
        sBh[f * PLDA + c4 * 2]     = pk16(h0, h1);
        sBh[f * PLDA + c4 * 2 + 1] = pk16(h2, h3);
        sBl[f * PLDA + c4 * 2]     = pk16(l0, l1);
        sBl[f * PLDA + c4 * 2 + 1] = pk16(l2, l3);
    }
    // A = raw q/k planes [128][32 u32] + diag
#pragma unroll
    for (int i = 0; i < 16; i++) {
        int u = tid + i * 256;            // 0..4095
        int r = u >> 5, cc = u & 31;      // whole warp shares row r
        size_t gi = ((size_t)bh * NTOK + row0 + r) * 32 + cc;
        uint32_t vh = ph[gi], vl = pl[gi];
        sAh[r * PLDA + cc] = vh;
        sAl[r * PLDA + cc] = vl;
        float e0 = fbf16((uint16_t)(vh & 0xFFFF)) + fbf16((uint16_t)(vl & 0xFFFF));
        float e1 = fbf16((uint16_t)(vh >> 16)) + fbf16((uint16_t)(vl >> 16));
        float ds = e0 * e0 + e1 * e1;
#pragma unroll
        for (int o = 1; o < 32; o <<= 1) ds += __shfl_xor_sync(0xffffffffu, ds, o);
        if (lane == 0) s_diag[r] = 0.0625f * ds;   // 0.5*DN^2*|q|^2
    }
    __syncthreads();

    float c[2][16][4];
#pragma unroll
    for (int i = 0; i < 2; i++)
#pragma unroll
        for (int j = 0; j < 16; j++)
#pragma unroll
            for (int t = 0; t < 4; t++) c[i][j][t] = 0.f;

#pragma unroll
    for (int ks = 0; ks < 4; ks++) {
        const int kb = ks * 8 + tig;
        uint32_t ah[2][4], al[2][4];
#pragma unroll
        for (int i = 0; i < 2; i++) {
            int b0 = (m0 + i * 16 + lr) * PLDA + kb;
            ah[i][0] = sAh[b0];             ah[i][1] = sAh[b0 + 8 * PLDA];
            ah[i][2] = sAh[b0 + 4];         ah[i][3] = sAh[b0 + 8 * PLDA + 4];
            al[i][0] = sAl[b0];             al[i][1] = sAl[b0 + 8 * PLDA];
            al[i][2] = sAl[b0 + 4];         al[i][3] = sAl[b0 + 8 * PLDA + 4];
        }
#pragma unroll
        for (int j = 0; j < 16; j++) {
            int nb = (n0 + j * 8 + lr) * PLDA + kb;
            uint32_t bh2[2] = { sBh[nb], sBh[nb + 4] };
            uint32_t bl2[2] = { sBl[nb], sBl[nb + 4] };
            mma_bf16(c[0][j], ah[0], bh2);
            mma_bf16(c[1][j], ah[1], bh2);
            mma_bf16(c[0][j], ah[0], bl2);
            mma_bf16(c[1][j], ah[1], bl2);
            mma_bf16(c[0][j], al[0], bh2);
            mma_bf16(c[1][j], al[1], bh2);
        }
    }

    if (is_query) {
#pragma unroll
        for (int i = 0; i < 2; i++)
#pragma unroll
            for (int rr = 0; rr < 2; rr++) {
                float mx = -1e30f;
#pragma unroll
                for (int j = 0; j < 16; j++) {
                    mx = fmaxf(mx, c[i][j][rr * 2]);
                    mx = fmaxf(mx, c[i][j][rr * 2 + 1]);
                }
                mx = fmaxf(mx, __shfl_xor_sync(0xffffffffu, mx, 1));
                mx = fmaxf(mx, __shfl_xor_sync(0xffffffffu, mx, 2));
                if (tig == 0)
                    s_rmax[(wid >> 2) * 128 + m0 + i * 16 + lr + rr * 8] = mx;
            }
        __syncthreads();
#pragma unroll
        for (int i = 0; i < 2; i++)
#pragma unroll
            for (int rr = 0; rr < 2; rr++) {
                const int r = m0 + i * 16 + lr + rr * 8;
                const float m = fmaxf(s_rmax[r], s_rmax[128 + r]);
                const float dia = s_diag[r];
                size_t base = ((size_t)bh * NTOK + row0 + r) * 128 + (n0 >> 1);
                uint32_t* dsth = g_qph + base;
                uint32_t* dstl = g_qpl + base;
#pragma unroll
                for (int j = 0; j < 16; j++) {
                    float v0 = RATIO * (expf(c[i][j][rr * 2]     - dia - m) + FEPS);
                    float v1 = RATIO * (expf(c[i][j][rr * 2 + 1] - dia - m) + FEPS);
                    uint16_t h0, l0, h1, l1;
                    spbf(v0, h0, l0); spbf(v1, h1, l1);
                    dsth[j * 4 + tig] = pk16(h0, h1);
                    dstl[j * 4 + tig] = pk16(l0, l1);
                }
            }
    } else {
        float bm = -1e30f;
#pragma unroll
        for (int i = 0; i < 2; i++)
#pragma unroll
            for (int j = 0; j < 16; j++)
#pragma unroll
                for (int t = 0; t < 4; t++) bm = fmaxf(bm, c[i][j][t]);
#pragma unroll
        for (int o = 16; o >= 1; o >>= 1) bm = fmaxf(bm, __shfl_xor_sync(0xffffffffu, bm, o));
        if (lane == 0) s_rmax[wid] = bm;
        __syncthreads();
        if (tid == 0) {
            float m = s_rmax[0];
#pragma unroll
            for (int w = 1; w < 8; w++) m = fmaxf(m, s_rmax[w]);
            g_kmax_part[bh * 512 + blockIdx.x] = m;
        }
        if (tid < 128) g_diag[(size_t)bh * NTOK + row0 + tid] = s_diag[tid];
#pragma unroll
        for (int i = 0; i < 2; i++)
#pragma unroll
            for (int rr = 0; rr < 2; rr++) {
                const int r = m0 + i * 16 + lr + rr * 8;
                float* dst = g_dd + ((size_t)bh * NTOK + row0 + r) * 256 + n0;
#pragma unroll
                for (int j = 0; j < 16; j++)
                    *(float2*)(dst + j * 8 + tig * 2) =
                        make_float2(c[i][j][rr * 2], c[i][j][rr * 2 + 1]);
            }
    }
}

__global__ void kmax_reduce() {
    __shared__ float s[8];
    int bh = blockIdx.x, tid = threadIdx.x;
    float v = (tid < 128) ? g_kmax_part[bh * 512 + tid] : -1e30f;
#pragma unroll
    for (int o = 1; o < 32; o <<= 1) v = fmaxf(v, __shfl_xor_sync(0xffffffffu, v, o));
    if ((tid & 31) == 0) s[tid >> 5] = v;
    __syncthreads();
    if (tid == 0) {
        float m = s[0];
#pragma unroll
        for (int w = 1; w < 8; w++) m = fmaxf(m, s[w]);
        g_kmax[bh] = m;
    }
}

// kp=ratio*(exp(dd-diag-m)+eps); write kpT hi/lo planes; accumulate ksum
__global__ void __launch_bounds__(256) kp_finalize_t() {
    extern __shared__ uint16_t skp[];   // hi [256][130], lo [256][130]
    uint16_t* skph = skp;
    uint16_t* skpl = skp + 256 * 130;
    const int tid = threadIdx.x;
    const int bh = blockIdx.y;
    const int row0 = blockIdx.x * 128;
    const float m = g_kmax[bh];
    const int f = tid;
    float ksum = 0.f;
    for (int g = 0; g < 128; g++) {
        float dia = g_diag[(size_t)bh * NTOK + row0 + g];
        float dd = g_dd[((size_t)bh * NTOK + row0 + g) * 256 + f];
        float kp = RATIO * (expf(dd - dia - m) + FEPS);
        ksum += kp;
        uint16_t h, l;
        spbf(kp, h, l);
        skph[f * 130 + g] = h;
        skpl[f * 130 + g] = l;
    }
    atomicAdd(&g_ksum[bh * 256 + f], ksum);
    __syncthreads();
    const int wid = tid >> 5, lane = tid & 31;
#pragma unroll 4
    for (int ff = 0; ff < 32; ff++) {
        int fr = wid * 32 + ff;
        const uint32_t* srh = (const uint32_t*)&skph[fr * 130];
        const uint32_t* srl = (const uint32_t*)&skpl[fr * 130];
        size_t base = ((size_t)bh * 256 + fr) * 8192 + (row0 >> 1);
        g_kpTh[base + lane] = srh[lane];
        g_kpTh[base + lane + 32] = srh[lane + 32];
        g_kpTl[base + lane] = srl[lane];
        g_kpTl[base + lane + 32] = srl[lane + 32];
    }
}

// ============= ctx via mma (split-3): C[f][d] += kpT @ vT^T =============
__global__ void __launch_bounds__(256) ctx_mma() {
    extern __shared__ uint32_t csm[];
    uint32_t* sAh = csm;                 // 256*20
    uint32_t* sAl = sAh + 5120;
    uint32_t* sBh = sAl + 5120;          // 64*20
    uint32_t* sBl = sBh + 1280;
    float* sv = (float*)(sBl + 1280);    // 32*68
    const int tid = threadIdx.x;
    const int wid = tid >> 5, lane = tid & 31;
    const int lr = lane >> 2, tig = lane & 3;
    const int m0 = (wid & 3) * 64;
    const int n0w = (wid >> 2) * 32;
    const int bh = blockIdx.y;
    const int kc = blockIdx.x;

    float c[4][4][4];
#pragma unroll
    for (int i = 0; i < 4; i++)
#pragma unroll
        for (int j = 0; j < 4; j++)
#pragma unroll
            for (int t = 0; t < 4; t++) c[i][j][t] = 0.f;

    for (int nc = 0; nc < 64; nc++) {
        const int nbase = kc * 2048 + nc * 32;
#pragma unroll
        for (int i = 0; i < 16; i++) {
            int u = tid + i * 256;
            int fr = u >> 4, cw = u & 15;
            size_t gi = ((size_t)bh * 256 + fr) * 8192 + (nbase >> 1) + cw;
            sAh[fr * 20 + cw] = g_kpTh[gi];
            sAl[fr * 20 + cw] = g_kpTl[gi];
        }
#pragma unroll
        for (int i = 0; i < 2; i++) {
            int u = tid + i * 256;
            int n = u >> 4, c4 = u & 15;
            *(float4*)&sv[n * 68 + c4 * 4] =
                *(const float4*)(g_v + ((size_t)bh * NTOK + nbase + n) * 64 + c4 * 4);
        }
        __syncthreads();
#pragma unroll
        for (int i = 0; i < 4; i++) {
            int u = tid + i * 256;
            int d = u >> 4, nw = u & 15;
            uint16_t h0, l0, h1, l1;
            spbf(sv[(nw * 2) * 68 + d], h0, l0);
            spbf(sv[(nw * 2 + 1) * 68 + d], h1, l1);
            sBh[d * 20 + nw] = pk16(h0, h1);
            sBl[d * 20 + nw] = pk16(l0, l1);
        }
        __syncthreads();
#pragma unroll
        for (int ks = 0; ks < 2; ks++) {
            const int kb = ks * 8 + tig;
            uint32_t ah[4][4], al[4][4];
#pragma unroll
            for (int i = 0; i < 4; i++) {
                int b0 = (m0 + i * 16 + lr) * 20 + kb;
                ah[i][0] = sAh[b0];       ah[i][1] = sAh[b0 + 160];
                ah[i][2] = sAh[b0 + 4];   ah[i][3] = sAh[b0 + 164];
                al[i][0] = sAl[b0];       al[i][1] = sAl[b0 + 160];
                al[i][2] = sAl[b0 + 4];   al[i][3] = sAl[b0 + 164];
            }
#pragma unroll
            for (int j = 0; j < 4; j++) {
                int nb = (n0w + j * 8 + lr) * 20 + kb;
                uint32_t bh2[2] = { sBh[nb], sBh[nb + 4] };
                uint32_t bl2[2] = { sBl[nb], sBl[nb + 4] };
#pragma unroll
                for (int i = 0; i < 4; i++) {
                    mma_bf16(c[i][j], ah[i], bh2);
                    mma_bf16(c[i][j], ah[i], bl2);
                    mma_bf16(c[i][j], al[i], bh2);
                }
            }
        }
        __syncthreads();
    }
#pragma unroll
    for (int i = 0; i < 4; i++)
#pragma unroll
        for (int j = 0; j < 4; j++)
#pragma unroll
            for (int rr = 0; rr < 2; rr++) {
                int fr = m0 + i * 16 + lr + rr * 8;
                int d = n0w + j * 8 + tig * 2;
                atomicAdd(&g_ctx[((size_t)bh * 256 + fr) * 64 + d], c[i][j][rr * 2]);
                atomicAdd(&g_ctx[((size_t)bh * 256 + fr) * 64 + d + 1], c[i][j][rr * 2 + 1]);
            }
}

__global__ void ctxT_kernel() {
    const int bh = blockIdx.x, tid = threadIdx.x;
    for (int i = 0; i < 64; i++) {
        int u = tid + i * 256;
        int f = u >> 6, d = u & 63;
        float v = g_ctx[((size_t)bh * 256 + f) * 64 + d];
        uint16_t h, l;
        spbf(v, h, l);
        size_t di = ((size_t)bh * 64 + d) * 256 + f;
        ((uint16_t*)g_ctxTh)[di] = h;
        ((uint16_t*)g_ctxTl)[di] = l;
    }
}

// ============= attn via mma (split-3) + fused d_inv, plane output =============
__global__ void __launch_bounds__(256) attn_mma() {
    __shared__ uint32_t sAh[128 * 20];
    __shared__ uint32_t sAl[128 * 20];
    __shared__ uint32_t sBh[64 * 20];
    __shared__ uint32_t sBl[64 * 20];
    __shared__ float sk[32];
    __shared__ float sdsum[128];
    const int tid = threadIdx.x;
    const int wid = tid >> 5, lane = tid & 31;
    const int lr = lane >> 2, tig = lane & 3;
    const int m0 = (wid & 3) * 32;
    const int n0w = (wid >> 2) * 32;
    const int bh = blockIdx.y;
    const int row0 = blockIdx.x * 128;

    float c[2][4][4];
#pragma unroll
    for (int i = 0; i < 2; i++)
#pragma unroll
        for (int j = 0; j < 4; j++)
#pragma unroll
            for (int t = 0; t < 4; t++) c[i][j][t] = 0.f;
    float dsum = 0.f;

    for (int fc = 0; fc < 8; fc++) {
#pragma unroll
        for (int i = 0; i < 8; i++) {
            int u = tid + i * 256;
            int n = u >> 4, cw = u & 15;
            size_t gi = ((size_t)bh * NTOK + row0 + n) * 128 + fc * 16 + cw;
            sAh[n * 20 + cw] = g_qph[gi];
            sAl[n * 20 + cw] = g_qpl[gi];
        }
#pragma unroll
        for (int i = 0; i < 4; i++) {
            int u = tid + i * 256;
            int d = u >> 4, cw = u & 15;
            size_t gi = ((size_t)bh * 64 + d) * 128 + fc * 16 + cw;
            sBh[d * 20 + cw] = g_ctxTh[gi];
            sBl[d * 20 + cw] = g_ctxTl[gi];
        }
        if (tid < 32) sk[tid] = g_ksum[bh * 256 + fc * 32 + tid];
        __syncthreads();
        if (tid < 128) {
#pragma unroll
            for (int w = 0; w < 16; w++) {
                uint32_t phh = sAh[tid * 20 + w];
                uint32_t pll = sAl[tid * 20 + w];
                dsum += (fbf16((uint16_t)(phh & 0xFFFF)) + fbf16((uint16_t)(pll & 0xFFFF))) * sk[w * 2]
                      + (fbf16((uint16_t)(phh >> 16)) + fbf16((uint16_t)(pll >> 16))) * sk[w * 2 + 1];
            }
        }
#pragma unroll
        for (int ks = 0; ks < 2; ks++) {
            const int kb = ks * 8 + tig;
            uint32_t ah[2][4], al[2][4];
#pragma unroll
            for (int i = 0; i < 2; i++) {
                int b0 = (m0 + i * 16 + lr) * 20 + kb;
                ah[i][0] = sAh[b0];       ah[i][1] = sAh[b0 + 160];
                ah[i][2] = sAh[b0 + 4];   ah[i][3] = sAh[b0 + 164];
                al[i][0] = sAl[b0];       al[i][1] = sAl[b0 + 160];
                al[i][2] = sAl[b0 + 4];   al[i][3] = sAl[b0 + 164];
            }
#pragma unroll
            for (int j = 0; j < 4; j++) {
                int nb = (n0w + j * 8 + lr) * 20 + kb;
                uint32_t bh2[2] = { sBh[nb], sBh[nb + 4] };
                uint32_t bl2[2] = { sBl[nb], sBl[nb + 4] };
#pragma unroll
                for (int i = 0; i < 2; i++) {
                    mma_bf16(c[i][j], ah[i], bh2);
                    mma_bf16(c[i][j], ah[i], bl2);
                    mma_bf16(c[i][j], al[i], bh2);
                }
            }
        }
        __syncthreads();
    }
    if (tid < 128) sdsum[tid] = dsum;
    __syncthreads();

    const int b = bh >> 3, h = bh & 7;
#pragma unroll
    for (int i = 0; i < 2; i++)
#pragma unroll
        for (int rr = 0; rr < 2; rr++) {
            const int r = m0 + i * 16 + lr + rr * 8;
            const float rinv = 1.0f / sdsum[r];
            const int n = row0 + r;
            size_t rowbase = ((size_t)b * NTOK + n) * 256 + ((h * 64 + n0w) >> 1);
#pragma unroll
            for (int j = 0; j < 4; j++) {
                uint16_t h0, l0, h1, l1;
                spbf(c[i][j][rr * 2] * rinv, h0, l0);
                spbf(c[i][j][rr * 2 + 1] * rinv, h1, l1);
                g_attnh[rowbase + j * 4 + tig] = pk16(h0, h1);
                g_attnl[rowbase + j * 4 + tig] = pk16(l0, l1);
            }
        }
}

// ---------------- prep kernels ----------------
__global__ void zero_accum() {
    int idx = blockIdx.x * 256 + threadIdx.x;
    if (idx < 524288) g_ctx[idx] = 0.f;
    else if (idx < 524288 + 8192) g_ksum[idx - 524288] = 0.f;
}

__global__ void split_x(const float* __restrict__ x) {
    int idx = blockIdx.x * 256 + threadIdx.x;   // 8388608
    int row = idx >> 7, cp = idx & 127;
    float v0 = x[(size_t)row * 256 + 2 * cp];
    float v1 = x[(size_t)row * 256 + 2 * cp + 1];
    uint16_t h0, l0, h1, l1;
    spbf(v0, h0, l0); spbf(v1, h1, l1);
    g_xh[idx] = pk16(h0, h1);
    g_xl[idx] = pk16(l0, l1);
}

__global__ void wt_split(const float* __restrict__ Wq, const float* __restrict__ Wk,
                         const float* __restrict__ Wv) {
    int idx = blockIdx.x * 256 + threadIdx.x;   // 196608 = 3*512*128
    int z = idx >> 16;
    int rem = idx & 65535;
    int n = rem >> 7, cp = rem & 127;
    const float* W = z == 0 ? Wq : (z == 1 ? Wk : Wv);
    float v0 = W[(size_t)(2 * cp) * 512 + n];
    float v1 = W[(size_t)(2 * cp + 1) * 512 + n];
    uint16_t h0, l0, h1, l1;
    spbf(v0, h0, l0); spbf(v1, h1, l1);
    g_wTh[idx] = pk16(h0, h1);
    g_wTl[idx] = pk16(l0, l1);
}

__global__ void wpT_kernel(const float* __restrict__ Wp) {
    int idx = blockIdx.x * 256 + threadIdx.x;
    int n = idx >> 8, c = idx & 255;
    g_wpT[idx] = Wp[c * 256 + n];
}

__global__ void wowp_kernel(const float* __restrict__ Wo) {
    __shared__ float swo[256];
    int k = blockIdx.x, n = threadIdx.x;
    swo[n] = Wo[(size_t)k * 256 + n];
    __syncthreads();
    float acc = 0.f;
    const float* wp = g_wpT + n * 256;
#pragma unroll 4
    for (int cc = 0; cc < 256; cc += 4) {
        float4 a = *(const float4*)(swo + cc);
        float4 bb = *(const float4*)(wp + cc);
        acc += a.x * bb.x + a.y * bb.y + a.z * bb.z + a.w * bb.w;
    }
    g_wopT[n * 512 + k] = acc;
}

__global__ void wopT_split() {
    int idx = blockIdx.x * 256 + threadIdx.x;   // 65536 = 256*256
    int n = idx >> 8, cp = idx & 255;
    float v0 = g_wopT[n * 512 + 2 * cp];
    float v1 = g_wopT[n * 512 + 2 * cp + 1];
    uint16_t h0, l0, h1, l1;
    spbf(v0, h0, l0); spbf(v1, h1, l1);
    g_wopTh[idx] = pk16(h0, h1);
    g_wopTl[idx] = pk16(l0, l1);
}

__global__ void b2s_kernel(const float* __restrict__ bo, const float* __restrict__ bp) {
    int n = threadIdx.x;
    float a = 0.f, ssum = 0.f;
    const float* wp = g_wpT + n * 256;
    for (int cc = 0; cc < 256; cc++) {
        float w = wp[cc];
        a += bo[cc] * w;
        ssum += w;
    }
    g_b2[n] = a + bp[n];
    g_s[n] = ssum;
}

// ---------------- launch ----------------
extern "C" void kernel_launch(void* const* d_in, const int* in_sizes, int n_in,
                              void* d_out, int out_size) {
    (void)in_sizes; (void)n_in; (void)out_size;
    const float* x    = (const float*)d_in[0];
    const float* Wq   = (const float*)d_in[1];
    const float* Wk   = (const float*)d_in[2];
    const float* Wv   = (const float*)d_in[3];
    const float* Wo   = (const float*)d_in[4];
    const float* bo   = (const float*)d_in[5];
    const float* proj = (const float*)d_in[6];
    const float* Wp   = (const float*)d_in[7];
    const float* bp   = (const float*)d_in[8];
    const float* btab = (const float*)d_in[9];
    float* out = (float*)d_out;

    cudaFuncSetAttribute(gemm2, cudaFuncAttributeMaxDynamicSharedMemorySize, 81920);
    cudaFuncSetAttribute(phi_mma, cudaFuncAttributeMaxDynamicSharedMemorySize, 112128);
    cudaFuncSetAttribute(kp_finalize_t, cudaFuncAttributeMaxDynamicSharedMemorySize, 133120);
    cudaFuncSetAttribute(ctx_mma, cudaFuncAttributeMaxDynamicSharedMemorySize, 59904);

    zero_accum<<<2081, 256>>>();
    split_x<<<32768, 256>>>(x);
    wt_split<<<768, 256>>>(Wq, Wk, Wv);
    wpT_kernel<<<256, 256>>>(Wp);
    wowp_kernel<<<512, 256>>>(Wo);
    wopT_split<<<256, 256>>>();
    b2s_kernel<<<1, 256>>>(bo, bp);

    gemm2<<<dim3(4, 512, 3), 256, 81920>>>(256, 1, nullptr, nullptr);

    phi_mma<<<dim3(128, 32), 256, 112128>>>(proj, 1);
    phi_mma<<<dim3(128, 32), 256, 112128>>>(proj, 0);
    kmax_reduce<<<32, 256>>>();
    kp_finalize_t<<<dim3(128, 32), 256, 133120>>>();
    ctx_mma<<<dim3(8, 32), 256, 59904>>>();
    ctxT_kernel<<<32, 256>>>();
    attn_mma<<<dim3(128, 32), 256>>>();

    gemm2<<<dim3(2, 512, 1), 256, 81920>>>(512, 0, btab, out);
}

// round 13
// speedup vs baseline: 2.7209x; 1.3573x over previous
#include <cuda_runtime.h>
#include <cuda_bf16.h>
#include <cuda_fp16.h>
#include <cstdint>
#include <cmath>

#define NTOK 16384
#define DN 0.3535533905932738f
#define RATIO 0.0625f
#define FEPS 1e-4f

// ---------------- device scratch ----------------
__device__ uint32_t g_xh[8388608], g_xl[8388608];          // x planes [65536][128]
__device__ uint32_t g_wTh[196608], g_wTl[196608];          // [3][512][128]
__device__ uint32_t g_wopTh[65536], g_wopTl[65536];        // [256][256]
__device__ uint32_t g_qh[16777216], g_ql[16777216];        // [32][16384][32]
__device__ uint32_t g_kh[16777216], g_kl[16777216];
__device__ uint32_t g_attnh[16777216], g_attnl[16777216];  // [65536][256] bf16 planes
__device__ float g_v[33554432];                            // [32][16384][64]
__device__ uint32_t g_qpf16[67108864];                     // qp fp16 [32][16384][128]
__device__ uint32_t g_kpf16[67108864];                     // kp fp16 [32][16384][128]
__device__ uint32_t g_ctxTf16[262144];                     // ctxT fp16 [32][64][128]
__device__ float g_kmax_part[16384];
__device__ float g_kmax[32];
__device__ float g_ksum[8192];                             // [32][256]
__device__ float g_ctx[524288];                            // [32][256][64]
__device__ float g_wpT[65536];
__device__ float g_wopT[131072];
__device__ float g_b2[256];
__device__ float g_s[256];

// ================= helpers =================
__device__ __forceinline__ uint32_t pk16(uint16_t a, uint16_t b) {
    return (uint32_t)a | ((uint32_t)b << 16);
}
__device__ __forceinline__ void spbf(float x, uint16_t& h, uint16_t& l) {
    __nv_bfloat16 hb = __float2bfloat16_rn(x);
    h = __bfloat16_as_ushort(hb);
    l = __bfloat16_as_ushort(__float2bfloat16_rn(x - __bfloat162float(hb)));
}
__device__ __forceinline__ float fbf16(uint16_t u) {
    return __bfloat162float(__ushort_as_bfloat16(u));
}
__device__ __forceinline__ uint16_t f16u(float x) {
    return __half_as_ushort(__float2half_rn(x));
}
__device__ __forceinline__ float uf16(uint16_t u) {
    return __half2float(__ushort_as_half(u));
}
__device__ __forceinline__ void mma_bf16(float* c, const uint32_t* a, const uint32_t* b) {
    asm volatile(
        "mma.sync.aligned.m16n8k16.row.col.f32.bf16.bf16.f32 "
        "{%0,%1,%2,%3}, {%4,%5,%6,%7}, {%8,%9}, {%0,%1,%2,%3};"
        : "+f"(c[0]), "+f"(c[1]), "+f"(c[2]), "+f"(c[3])
        : "r"(a[0]), "r"(a[1]), "r"(a[2]), "r"(a[3]), "r"(b[0]), "r"(b[1]));
}
__device__ __forceinline__ void mma_f16(float* c, const uint32_t* a, const uint32_t* b) {
    asm volatile(
        "mma.sync.aligned.m16n8k16.row.col.f32.f16.f16.f32 "
        "{%0,%1,%2,%3}, {%4,%5,%6,%7}, {%8,%9}, {%0,%1,%2,%3};"
        : "+f"(c[0]), "+f"(c[1]), "+f"(c[2]), "+f"(c[3])
        : "r"(a[0]), "r"(a[1]), "r"(a[2]), "r"(a[3]), "r"(b[0]), "r"(b[1]));
}
__device__ __forceinline__ uint32_t s2u(const void* p) {
    return (uint32_t)__cvta_generic_to_shared(p);
}
__device__ __forceinline__ void ldm_x4(uint32_t* r, uint32_t addr) {
    asm volatile("ldmatrix.sync.aligned.m8n8.x4.shared.b16 {%0,%1,%2,%3}, [%4];"
        : "=r"(r[0]), "=r"(r[1]), "=r"(r[2]), "=r"(r[3]) : "r"(addr));
}
__device__ __forceinline__ void cpa16(uint32_t dst, const void* src) {
    asm volatile("cp.async.ca.shared.global [%0], [%1], 16;" :: "r"(dst), "l"(src));
}
__device__ __forceinline__ void cpa_commit() { asm volatile("cp.async.commit_group;"); }
template <int N> __device__ __forceinline__ void cpa_wait() {
    asm volatile("cp.async.wait_group %0;" :: "n"(N));
}

// ============= pre-split cp.async+ldmatrix GEMM (verified R12) =============
#define GLD 20
__device__ __forceinline__ void gemm2_issue(
    const uint32_t* pA0, const uint32_t* pA1,
    const uint32_t* pB0, const uint32_t* pB1,
    int Ku, int row0, int col0, int st, int stage,
    uint32_t sbase, int tid) {
#pragma unroll
    for (int i = 0; i < 8; i++) {
        int u = tid + i * 256;
        int pl = u >> 9;
        int t = u & 511;
        int row = t >> 2, c4 = (t & 3) * 4;
        const uint32_t* src;
        if (pl == 0)      src = pA0 + (size_t)(row0 + row) * Ku + st * 16 + c4;
        else if (pl == 1) src = pA1 + (size_t)(row0 + row) * Ku + st * 16 + c4;
        else if (pl == 2) src = pB0 + (size_t)(col0 + row) * Ku + st * 16 + c4;
        else              src = pB1 + (size_t)(col0 + row) * Ku + st * 16 + c4;
        uint32_t dst = sbase + (uint32_t)(stage * 10240 + pl * 2560 + row * GLD + c4) * 4;
        cpa16(dst, src);
    }
    cpa_commit();
}

__global__ void __launch_bounds__(256) gemm2(
    int K, int qkv_mode, const float* __restrict__ btab, float* __restrict__ dout) {
    extern __shared__ uint32_t gsm[];
    const uint32_t sbase = s2u(gsm);
    const int tid = threadIdx.x;
    const int wid = tid >> 5, lane = tid & 31;
    const int lr = lane >> 2, tig = lane & 3;
    const int m0 = (wid & 3) * 32;
    const int n0 = (wid >> 2) * 64;
    const int row0 = blockIdx.y * 128;
    const int col0 = blockIdx.x * 128;

    const uint32_t *pA0, *pA1, *pB0, *pB1;
    if (qkv_mode) {
        pA0 = g_xh; pA1 = g_xl;
        pB0 = g_wTh + (size_t)blockIdx.z * 65536;
        pB1 = g_wTl + (size_t)blockIdx.z * 65536;
    } else {
        pA0 = g_attnh; pA1 = g_attnl;
        pB0 = g_wopTh; pB1 = g_wopTl;
    }
    const int Ku = K >> 1;
    const int steps = K >> 5;

    float c[2][8][4];
#pragma unroll
    for (int i = 0; i < 2; i++)
#pragma unroll
        for (int j = 0; j < 8; j++)
#pragma unroll
            for (int t = 0; t < 4; t++) c[i][j][t] = 0.f;

    gemm2_issue(pA0, pA1, pB0, pB1, Ku, row0, col0, 0, 0, sbase, tid);

    for (int st = 0; st < steps; st++) {
        if (st + 1 < steps) {
            gemm2_issue(pA0, pA1, pB0, pB1, Ku, row0, col0, st + 1, (st + 1) & 1, sbase, tid);
            cpa_wait<1>();
        } else {
            cpa_wait<0>();
        }
        __syncthreads();
        const uint32_t stoff = (uint32_t)((st & 1) * 10240) * 4;
        const uint32_t AhB = sbase + stoff;
        const uint32_t AlB = AhB + 2560 * 4;
        const uint32_t BhB = AhB + 5120 * 4;
        const uint32_t BlB = AhB + 7680 * 4;
#pragma unroll
        for (int ks = 0; ks < 2; ks++) {
            uint32_t ah[2][4], al[2][4];
#pragma unroll
            for (int i = 0; i < 2; i++) {
                uint32_t ro = (uint32_t)((m0 + i * 16 + (lane & 15)) * GLD) * 4
                              + ks * 32 + (lane >> 4) * 16;
                ldm_x4(ah[i], AhB + ro);
                ldm_x4(al[i], AlB + ro);
            }
#pragma unroll
            for (int jg = 0; jg < 4; jg++) {
                uint32_t ro = (uint32_t)((n0 + jg * 16 + (lane & 15)) * GLD) * 4
                              + ks * 32 + (lane >> 4) * 16;
                uint32_t bh4[4], bl4[4];
                ldm_x4(bh4, BhB + ro);
                ldm_x4(bl4, BlB + ro);
                uint32_t b0h[2] = { bh4[0], bh4[2] }, b1h[2] = { bh4[1], bh4[3] };
                uint32_t b0l[2] = { bl4[0], bl4[2] }, b1l[2] = { bl4[1], bl4[3] };
#pragma unroll
                for (int i = 0; i < 2; i++) {
                    mma_bf16(c[i][jg * 2],     ah[i], b0h);
                    mma_bf16(c[i][jg * 2],     ah[i], b0l);
                    mma_bf16(c[i][jg * 2],     al[i], b0h);
                    mma_bf16(c[i][jg * 2 + 1], ah[i], b1h);
                    mma_bf16(c[i][jg * 2 + 1], ah[i], b1l);
                    mma_bf16(c[i][jg * 2 + 1], al[i], b1h);
                }
            }
        }
        __syncthreads();
    }

#pragma unroll
    for (int i = 0; i < 2; i++) {
#pragma unroll
        for (int rr = 0; rr < 2; rr++) {
            const int r = row0 + m0 + i * 16 + lr + rr * 8;
            if (qkv_mode) {
                const int b = r >> 14, n = r & (NTOK - 1);
                const int z = blockIdx.z;
                if (z < 2) {
                    uint32_t* ph = z == 0 ? g_qh : g_kh;
                    uint32_t* pl = z == 0 ? g_ql : g_kl;
#pragma unroll
                    for (int j = 0; j < 8; j++) {
                        const int cg = col0 + n0 + j * 8 + tig * 2;
                        const int hh = cg >> 6, off = cg & 63;
                        size_t di = ((size_t)(b * 8 + hh) * NTOK + n) * 32 + (off >> 1);
                        uint16_t h0, l0, h1, l1;
                        spbf(c[i][j][rr * 2], h0, l0);
                        spbf(c[i][j][rr * 2 + 1], h1, l1);
                        ph[di] = pk16(h0, h1);
                        pl[di] = pk16(l0, l1);
                    }
                } else {
#pragma unroll
                    for (int j = 0; j < 8; j++) {
                        const int cg = col0 + n0 + j * 8 + tig * 2;
                        const int hh = cg >> 6, off = cg & 63;
                        float* dp = g_v + ((size_t)(b * 8 + hh) * NTOK + n) * 64 + off;
                        *(float2*)dp = make_float2(c[i][j][rr * 2], c[i][j][rr * 2 + 1]);
                    }
                }
            } else {
                const int n = r & (NTOK - 1);
                const int ii = n >> 7, jc = n & 127;
                int rel = ii - jc;
                rel = rel < -7 ? -7 : (rel > 7 ? 7 : rel);
                const float brow = btab[rel + 7];
#pragma unroll
                for (int j = 0; j < 8; j++) {
                    const int cg = col0 + n0 + j * 8 + tig * 2;
                    float2 b2v = *(const float2*)(g_b2 + cg);
                    float2 sv  = *(const float2*)(g_s + cg);
                    float* dp = dout + (size_t)r * 256 + cg;
                    *(float2*)dp = make_float2(c[i][j][rr * 2]     + b2v.x + brow * sv.x,
                                               c[i][j][rr * 2 + 1] + b2v.y + brow * sv.y);
                }
            }
        }
    }
}

// ============= phi via mma (split-3): dd = q @ (DN*proj)^T =============
// mode 1: query -> exp(row max) -> g_qpf16
// mode 0: key pass A -> block max only (kmax_part)
// mode 2: key pass B -> exp(global max) -> g_kpf16
#define PLDA 36
__global__ void __launch_bounds__(256) phi_mma(const float* __restrict__ proj,
                                               int mode) {
    extern __shared__ uint32_t sm[];
    uint32_t* sAh = sm;
    uint32_t* sAl = sAh + 128 * PLDA;
    uint32_t* sBh = sAl + 128 * PLDA;
    uint32_t* sBl = sBh + 256 * PLDA;
    float* s_diag = (float*)(sBl + 256 * PLDA);
    float* s_rmax = s_diag + 128;

    const int tid = threadIdx.x;
    const int wid = tid >> 5, lane = tid & 31;
    const int lr = lane >> 2, tig = lane & 3;
    const int m0 = (wid & 3) * 32;
    const int n0 = (wid >> 2) * 128;
    const int bh = blockIdx.y;
    const int row0 = blockIdx.x * 128;
    const uint32_t* ph = (mode == 1) ? g_qh : g_kh;
    const uint32_t* pl = (mode == 1) ? g_ql : g_kl;

#pragma unroll
    for (int i = 0; i < 16; i++) {
        int u = tid + i * 256;
        int f = u >> 4, c4 = u & 15;
        float4 v = ((const float4*)proj)[u];
        v.x *= DN; v.y *= DN; v.z *= DN; v.w *= DN;
        uint16_t h0, h1, h2, h3, l0, l1, l2, l3;
        spbf(v.x, h0, l0); spbf(v.y, h1, l1); spbf(v.z, h2, l2); spbf(v.w, h3, l3);
        sBh[f * PLDA + c4 * 2]     = pk16(h0, h1);
        sBh[f * PLDA + c4 * 2 + 1] = pk16(h2, h3);
        sBl[f * PLDA + c4 * 2]     = pk16(l0, l1);
        sBl[f * PLDA + c4 * 2 + 1] = pk16(l2, l3);
    }
#pragma unroll
    for (int i = 0; i < 16; i++) {
        int u = tid + i * 256;
        int r = u >> 5, cc = u & 31;
        size_t gi = ((size_t)bh * NTOK + row0 + r) * 32 + cc;
        uint32_t vh = ph[gi], vl = pl[gi];
        sAh[r * PLDA + cc] = vh;
        sAl[r * PLDA + cc] = vl;
        float e0 = fbf16((uint16_t)(vh & 0xFFFF)) + fbf16((uint16_t)(vl & 0xFFFF));
        float e1 = fbf16((uint16_t)(vh >> 16)) + fbf16((uint16_t)(vl >> 16));
        float ds = e0 * e0 + e1 * e1;
#pragma unroll
        for (int o = 1; o < 32; o <<= 1) ds += __shfl_xor_sync(0xffffffffu, ds, o);
        if (lane == 0) s_diag[r] = 0.0625f * ds;   // 0.5*DN^2*|q|^2
    }
    __syncthreads();

    float c[2][16][4];
#pragma unroll
    for (int i = 0; i < 2; i++)
#pragma unroll
        for (int j = 0; j < 16; j++)
#pragma unroll
            for (int t = 0; t < 4; t++) c[i][j][t] = 0.f;

#pragma unroll
    for (int ks = 0; ks < 4; ks++) {
        const int kb = ks * 8 + tig;
        uint32_t ah[2][4], al[2][4];
#pragma unroll
        for (int i = 0; i < 2; i++) {
            int b0 = (m0 + i * 16 + lr) * PLDA + kb;
            ah[i][0] = sAh[b0];             ah[i][1] = sAh[b0 + 8 * PLDA];
            ah[i][2] = sAh[b0 + 4];         ah[i][3] = sAh[b0 + 8 * PLDA + 4];
            al[i][0] = sAl[b0];             al[i][1] = sAl[b0 + 8 * PLDA];
            al[i][2] = sAl[b0 + 4];         al[i][3] = sAl[b0 + 8 * PLDA + 4];
        }
#pragma unroll
        for (int j = 0; j < 16; j++) {
            int nb = (n0 + j * 8 + lr) * PLDA + kb;
            uint32_t bh2[2] = { sBh[nb], sBh[nb + 4] };
            uint32_t bl2[2] = { sBl[nb], sBl[nb + 4] };
            mma_bf16(c[0][j], ah[0], bh2);
            mma_bf16(c[1][j], ah[1], bh2);
            mma_bf16(c[0][j], ah[0], bl2);
            mma_bf16(c[1][j], ah[1], bl2);
            mma_bf16(c[0][j], al[0], bh2);
            mma_bf16(c[1][j], al[1], bh2);
        }
    }

    if (mode == 0) {
        // key pass A: block max only
        float bm = -1e30f;
#pragma unroll
        for (int i = 0; i < 2; i++)
#pragma unroll
            for (int j = 0; j < 16; j++)
#pragma unroll
                for (int t = 0; t < 4; t++) bm = fmaxf(bm, c[i][j][t]);
#pragma unroll
        for (int o = 16; o >= 1; o >>= 1) bm = fmaxf(bm, __shfl_xor_sync(0xffffffffu, bm, o));
        if (lane == 0) s_rmax[wid] = bm;
        __syncthreads();
        if (tid == 0) {
            float m = s_rmax[0];
#pragma unroll
            for (int w = 1; w < 8; w++) m = fmaxf(m, s_rmax[w]);
            g_kmax_part[bh * 512 + blockIdx.x] = m;
        }
    } else {
        float mg = 0.f;
        if (mode == 2) mg = g_kmax[bh];
        if (mode == 1) {
#pragma unroll
            for (int i = 0; i < 2; i++)
#pragma unroll
                for (int rr = 0; rr < 2; rr++) {
                    float mx = -1e30f;
#pragma unroll
                    for (int j = 0; j < 16; j++) {
                        mx = fmaxf(mx, c[i][j][rr * 2]);
                        mx = fmaxf(mx, c[i][j][rr * 2 + 1]);
                    }
                    mx = fmaxf(mx, __shfl_xor_sync(0xffffffffu, mx, 1));
                    mx = fmaxf(mx, __shfl_xor_sync(0xffffffffu, mx, 2));
                    if (tig == 0)
                        s_rmax[(wid >> 2) * 128 + m0 + i * 16 + lr + rr * 8] = mx;
                }
            __syncthreads();
        }
        uint32_t* dst0 = (mode == 1) ? g_qpf16 : g_kpf16;
#pragma unroll
        for (int i = 0; i < 2; i++)
#pragma unroll
            for (int rr = 0; rr < 2; rr++) {
                const int r = m0 + i * 16 + lr + rr * 8;
                const float m = (mode == 1) ? fmaxf(s_rmax[r], s_rmax[128 + r]) : mg;
                const float dia = s_diag[r];
                size_t base = ((size_t)bh * NTOK + row0 + r) * 128 + (n0 >> 1);
                uint32_t* dst = dst0 + base;
#pragma unroll
                for (int j = 0; j < 16; j++) {
                    float v0 = RATIO * (expf(c[i][j][rr * 2]     - dia - m) + FEPS);
                    float v1 = RATIO * (expf(c[i][j][rr * 2 + 1] - dia - m) + FEPS);
                    dst[j * 4 + tig] = pk16(f16u(v0), f16u(v1));
                }
            }
    }
}

__global__ void kmax_reduce() {
    __shared__ float s[8];
    int bh = blockIdx.x, tid = threadIdx.x;
    float v = (tid < 128) ? g_kmax_part[bh * 512 + tid] : -1e30f;
#pragma unroll
    for (int o = 1; o < 32; o <<= 1) v = fmaxf(v, __shfl_xor_sync(0xffffffffu, v, o));
    if ((tid & 31) == 0) s[tid >> 5] = v;
    __syncthreads();
    if (tid == 0) {
        float m = s[0];
#pragma unroll
        for (int w = 1; w < 8; w++) m = fmaxf(m, s[w]);
        g_kmax[bh] = m;
    }
}

// ============= ctx via mma (fp16 single): C[f][d] += kpT @ vT^T, fused ksum =============
__global__ void __launch_bounds__(256) ctx_mma() {
    extern __shared__ uint32_t csm[];
    uint32_t* sStage = csm;              // 32 * 129 (kp tile raw, padded)
    uint32_t* sA = sStage + 32 * 129;    // 256 * 20 (fp16 pairs over n)
    uint32_t* sB = sA + 5120;            // 64 * 20
    float* sv = (float*)(sB + 1280);     // 32 * 68
    const int tid = threadIdx.x;
    const int wid = tid >> 5, lane = tid & 31;
    const int lr = lane >> 2, tig = lane & 3;
    const int m0 = (wid & 3) * 64;
    const int n0w = (wid >> 2) * 32;
    const int bh = blockIdx.y;
    const int kc = blockIdx.x;

    float c[4][4][4];
#pragma unroll
    for (int i = 0; i < 4; i++)
#pragma unroll
        for (int j = 0; j < 4; j++)
#pragma unroll
            for (int t = 0; t < 4; t++) c[i][j][t] = 0.f;
    float fsum[16];
#pragma unroll
    for (int i = 0; i < 16; i++) fsum[i] = 0.f;

    const int fA = tid >> 4;       // 0..15 (f base / 16-group id)
    const int npA = tid & 15;

    for (int nc = 0; nc < 64; nc++) {
        const int nbase = kc * 2048 + nc * 32;
        // stage kp tile [32n][128w] raw (coalesced)
#pragma unroll
        for (int i = 0; i < 16; i++) {
            int u = tid + i * 256;
            int n = u >> 7, cw = u & 127;
            sStage[n * 129 + cw] = g_kpf16[((size_t)bh * NTOK + nbase + n) * 128 + cw];
        }
        // v tile [32][64] fp32
#pragma unroll
        for (int i = 0; i < 2; i++) {
            int u = tid + i * 256;
            int n = u >> 4, c4 = u & 15;
            *(float4*)&sv[n * 68 + c4 * 4] =
                *(const float4*)(g_v + ((size_t)bh * NTOK + nbase + n) * 64 + c4 * 4);
        }
        __syncthreads();
        // build A [256f][16 n-pairs] via 16-bit transpose reads + fused ksum
        {
            const uint16_t* st16 = (const uint16_t*)sStage;
#pragma unroll
            for (int i = 0; i < 16; i++) {
                int f = fA + i * 16;
                uint16_t a0 = st16[(2 * npA) * 258 + f];
                uint16_t a1 = st16[(2 * npA + 1) * 258 + f];
                sA[f * 20 + npA] = pk16(a0, a1);
                fsum[i] += uf16(a0) + uf16(a1);
            }
        }
        // build B [64d][16 n-pairs] fp16 (v transpose)
#pragma unroll
        for (int i = 0; i < 4; i++) {
            int u = tid + i * 256;
            int d = u >> 4, nw = u & 15;
            sB[d * 20 + nw] = pk16(f16u(sv[(nw * 2) * 68 + d]),
                                   f16u(sv[(nw * 2 + 1) * 68 + d]));
        }
        __syncthreads();
#pragma unroll
        for (int ks = 0; ks < 2; ks++) {
            const int kb = ks * 8 + tig;
            uint32_t a[4][4];
#pragma unroll
            for (int i = 0; i < 4; i++) {
                int b0 = (m0 + i * 16 + lr) * 20 + kb;
                a[i][0] = sA[b0];       a[i][1] = sA[b0 + 160];
                a[i][2] = sA[b0 + 4];   a[i][3] = sA[b0 + 164];
            }
#pragma unroll
            for (int j = 0; j < 4; j++) {
                int nb = (n0w + j * 8 + lr) * 20 + kb;
                uint32_t b2[2] = { sB[nb], sB[nb + 4] };
#pragma unroll
                for (int i = 0; i < 4; i++) mma_f16(c[i][j], a[i], b2);
            }
        }
        __syncthreads();
    }
    // ctx atomics
#pragma unroll
    for (int i = 0; i < 4; i++)
#pragma unroll
        for (int j = 0; j < 4; j++)
#pragma unroll
            for (int rr = 0; rr < 2; rr++) {
                int fr = m0 + i * 16 + lr + rr * 8;
                int d = n0w + j * 8 + tig * 2;
                atomicAdd(&g_ctx[((size_t)bh * 256 + fr) * 64 + d], c[i][j][rr * 2]);
                atomicAdd(&g_ctx[((size_t)bh * 256 + fr) * 64 + d + 1], c[i][j][rr * 2 + 1]);
            }
    // ksum: reduce over the 16 lanes sharing this f-set (lane&15 partners)
#pragma unroll
    for (int o = 1; o < 16; o <<= 1)
#pragma unroll
        for (int i = 0; i < 16; i++)
            fsum[i] += __shfl_xor_sync(0xffffffffu, fsum[i], o);
    if ((lane & 15) == 0) {
#pragma unroll
        for (int i = 0; i < 16; i++)
            atomicAdd(&g_ksum[bh * 256 + fA + i * 16], fsum[i]);
    }
}

__global__ void ctxT_kernel() {
    const int bh = blockIdx.x, tid = threadIdx.x;
    for (int i = 0; i < 64; i++) {
        int u = tid + i * 256;
        int f = u >> 6, d = u & 63;
        float v = g_ctx[((size_t)bh * 256 + f) * 64 + d];
        ((uint16_t*)g_ctxTf16)[(size_t)bh * 16384 + d * 256 + f] = f16u(v);
    }
}

// ============= attn via mma (fp16 single) + fused d_inv, bf16-split output =============
__global__ void __launch_bounds__(256) attn_mma() {
    __shared__ uint32_t sA[128 * 20];
    __shared__ uint32_t sB[64 * 20];
    __shared__ float sk[32];
    __shared__ float sdsum[128];
    const int tid = threadIdx.x;
    const int wid = tid >> 5, lane = tid & 31;
    const int lr = lane >> 2, tig = lane & 3;
    const int m0 = (wid & 3) * 32;
    const int n0w = (wid >> 2) * 32;
    const int bh = blockIdx.y;
    const int row0 = blockIdx.x * 128;

    float c[2][4][4];
#pragma unroll
    for (int i = 0; i < 2; i++)
#pragma unroll
        for (int j = 0; j < 4; j++)
#pragma unroll
            for (int t = 0; t < 4; t++) c[i][j][t] = 0.f;
    float dsum = 0.f;

    for (int fc = 0; fc < 8; fc++) {
#pragma unroll
        for (int i = 0; i < 8; i++) {
            int u = tid + i * 256;
            int n = u >> 4, cw = u & 15;
            sA[n * 20 + cw] = g_qpf16[((size_t)bh * NTOK + row0 + n) * 128 + fc * 16 + cw];
        }
#pragma unroll
        for (int i = 0; i < 4; i++) {
            int u = tid + i * 256;
            int d = u >> 4, cw = u & 15;
            sB[d * 20 + cw] = g_ctxTf16[(size_t)bh * 8192 + d * 128 + fc * 16 + cw];
        }
        if (tid < 32) sk[tid] = g_ksum[bh * 256 + fc * 32 + tid];
        __syncthreads();
        if (tid < 128) {
#pragma unroll
            for (int w = 0; w < 16; w++) {
                uint32_t p = sA[tid * 20 + w];
                dsum += uf16((uint16_t)(p & 0xFFFF)) * sk[w * 2]
                      + uf16((uint16_t)(p >> 16)) * sk[w * 2 + 1];
            }
        }
#pragma unroll
        for (int ks = 0; ks < 2; ks++) {
            const int kb = ks * 8 + tig;
            uint32_t a[2][4];
#pragma unroll
            for (int i = 0; i < 2; i++) {
                int b0 = (m0 + i * 16 + lr) * 20 + kb;
                a[i][0] = sA[b0];       a[i][1] = sA[b0 + 160];
                a[i][2] = sA[b0 + 4];   a[i][3] = sA[b0 + 164];
            }
#pragma unroll
            for (int j = 0; j < 4; j++) {
                int nb = (n0w + j * 8 + lr) * 20 + kb;
                uint32_t b2[2] = { sB[nb], sB[nb + 4] };
#pragma unroll
                for (int i = 0; i < 2; i++) mma_f16(c[i][j], a[i], b2);
            }
        }
        __syncthreads();
    }
    if (tid < 128) sdsum[tid] = dsum;
    __syncthreads();

    const int b = bh >> 3, h = bh & 7;
#pragma unroll
    for (int i = 0; i < 2; i++)
#pragma unroll
        for (int rr = 0; rr < 2; rr++) {
            const int r = m0 + i * 16 + lr + rr * 8;
            const float rinv = 1.0f / sdsum[r];
            const int n = row0 + r;
            size_t rowbase = ((size_t)b * NTOK + n) * 256 + ((h * 64 + n0w) >> 1);
#pragma unroll
            for (int j = 0; j < 4; j++) {
                uint16_t h0, l0, h1, l1;
                spbf(c[i][j][rr * 2] * rinv, h0, l0);
                spbf(c[i][j][rr * 2 + 1] * rinv, h1, l1);
                g_attnh[rowbase + j * 4 + tig] = pk16(h0, h1);
                g_attnl[rowbase + j * 4 + tig] = pk16(l0, l1);
            }
        }
}

// ---------------- prep kernels ----------------
__global__ void zero_accum() {
    int idx = blockIdx.x * 256 + threadIdx.x;
    if (idx < 524288) g_ctx[idx] = 0.f;
    else if (idx < 524288 + 8192) g_ksum[idx - 524288] = 0.f;
}

__global__ void split_x(const float* __restrict__ x) {
    int idx = blockIdx.x * 256 + threadIdx.x;
    int row = idx >> 7, cp = idx & 127;
    float v0 = x[(size_t)row * 256 + 2 * cp];
    float v1 = x[(size_t)row * 256 + 2 * cp + 1];
    uint16_t h0, l0, h1, l1;
    spbf(v0, h0, l0); spbf(v1, h1, l1);
    g_xh[idx] = pk16(h0, h1);
    g_xl[idx] = pk16(l0, l1);
}

__global__ void wt_split(const float* __restrict__ Wq, const float* __restrict__ Wk,
                         const float* __restrict__ Wv) {
    int idx = blockIdx.x * 256 + threadIdx.x;
    int z = idx >> 16;
    int rem = idx & 65535;
    int n = rem >> 7, cp = rem & 127;
    const float* W = z == 0 ? Wq : (z == 1 ? Wk : Wv);
    float v0 = W[(size_t)(2 * cp) * 512 + n];
    float v1 = W[(size_t)(2 * cp + 1) * 512 + n];
    uint16_t h0, l0, h1, l1;
    spbf(v0, h0, l0); spbf(v1, h1, l1);
    g_wTh[idx] = pk16(h0, h1);
    g_wTl[idx] = pk16(l0, l1);
}

__global__ void wpT_kernel(const float* __restrict__ Wp) {
    int idx = blockIdx.x * 256 + threadIdx.x;
    int n = idx >> 8, c = idx & 255;
    g_wpT[idx] = Wp[c * 256 + n];
}

__global__ void wowp_kernel(const float* __restrict__ Wo) {
    __shared__ float swo[256];
    int k = blockIdx.x, n = threadIdx.x;
    swo[n] = Wo[(size_t)k * 256 + n];
    __syncthreads();
    float acc = 0.f;
    const float* wp = g_wpT + n * 256;
#pragma unroll 4
    for (int cc = 0; cc < 256; cc += 4) {
        float4 a = *(const float4*)(swo + cc);
        float4 bb = *(const float4*)(wp + cc);
        acc += a.x * bb.x + a.y * bb.y + a.z * bb.z + a.w * bb.w;
    }
    g_wopT[n * 512 + k] = acc;
}

__global__ void wopT_split() {
    int idx = blockIdx.x * 256 + threadIdx.x;
    int n = idx >> 8, cp = idx & 255;
    float v0 = g_wopT[n * 512 + 2 * cp];
    float v1 = g_wopT[n * 512 + 2 * cp + 1];
    uint16_t h0, l0, h1, l1;
    spbf(v0, h0, l0); spbf(v1, h1, l1);
    g_wopTh[idx] = pk16(h0, h1);
    g_wopTl[idx] = pk16(l0, l1);
}

__global__ void b2s_kernel(const float* __restrict__ bo, const float* __restrict__ bp) {
    int n = threadIdx.x;
    float a = 0.f, ssum = 0.f;
    const float* wp = g_wpT + n * 256;
    for (int cc = 0; cc < 256; cc++) {
        float w = wp[cc];
        a += bo[cc] * w;
        ssum += w;
    }
    g_b2[n] = a + bp[n];
    g_s[n] = ssum;
}

// ---------------- launch ----------------
extern "C" void kernel_launch(void* const* d_in, const int* in_sizes, int n_in,
                              void* d_out, int out_size) {
    (void)in_sizes; (void)n_in; (void)out_size;
    const float* x    = (const float*)d_in[0];
    const float* Wq   = (const float*)d_in[1];
    const float* Wk   = (const float*)d_in[2];
    const float* Wv   = (const float*)d_in[3];
    const float* Wo   = (const float*)d_in[4];
    const float* bo   = (const float*)d_in[5];
    const float* proj = (const float*)d_in[6];
    const float* Wp   = (const float*)d_in[7];
    const float* bp   = (const float*)d_in[8];
    const float* btab = (const float*)d_in[9];
    float* out = (float*)d_out;

    cudaFuncSetAttribute(gemm2, cudaFuncAttributeMaxDynamicSharedMemorySize, 81920);
    cudaFuncSetAttribute(phi_mma, cudaFuncAttributeMaxDynamicSharedMemorySize, 112128);
    cudaFuncSetAttribute(ctx_mma, cudaFuncAttributeMaxDynamicSharedMemorySize, 50816);

    zero_accum<<<2081, 256>>>();
    split_x<<<32768, 256>>>(x);
    wt_split<<<768, 256>>>(Wq, Wk, Wv);
    wpT_kernel<<<256, 256>>>(Wp);
    wowp_kernel<<<512, 256>>>(Wo);
    wopT_split<<<256, 256>>>();
    b2s_kernel<<<1, 256>>>(bo, bp);

    gemm2<<<dim3(4, 512, 3), 256, 81920>>>(256, 1, nullptr, nullptr);

    phi_mma<<<dim3(128, 32), 256, 112128>>>(proj, 1);   // query -> qp fp16
    phi_mma<<<dim3(128, 32), 256, 112128>>>(proj, 0);   // key pass A: block max
    kmax_reduce<<<32, 256>>>();
    phi_mma<<<dim3(128, 32), 256, 112128>>>(proj, 2);   // key pass B -> kp fp16
    ctx_mma<<<dim3(8, 32), 256, 50816>>>();
    ctxT_kernel<<<32, 256>>>();
    attn_mma<<<dim3(128, 32), 256>>>();

    gemm2<<<dim3(2, 512, 1), 256, 81920>>>(512, 0, btab, out);
}

// round 14
// speedup vs baseline: 3.0199x; 1.1099x over previous
#include <cuda_runtime.h>
#include <cuda_bf16.h>
#include <cuda_fp16.h>
#include <cstdint>
#include <cmath>

#define NTOK 16384
#define DN 0.3535533905932738f
#define RATIO 0.0625f
#define FEPS 1e-4f
#define CEPS 6.25e-6f          // RATIO*FEPS

// ---------------- device scratch ----------------
__device__ uint32_t g_xh[8388608], g_xl[8388608];          // x planes [65536][128]
__device__ uint32_t g_wTh[196608], g_wTl[196608];          // [3][512][128]
__device__ uint32_t g_wopTh[65536], g_wopTl[65536];        // [256][256]
__device__ uint32_t g_qh[16777216], g_ql[16777216];        // [32][16384][32]
__device__ uint32_t g_kh[16777216], g_kl[16777216];
__device__ uint32_t g_attnh[16777216], g_attnl[16777216];  // [65536][256] bf16 planes
__device__ float g_v[33554432];                            // [32][16384][64]
__device__ uint32_t g_qpf16[67108864];                     // qp fp16 [32][16384][128]
__device__ uint32_t g_kpf16[67108864];                     // e_b fp16 [32][16384][128]
__device__ uint32_t g_ctxTf16[262144];                     // ctxT fp16 [32][64][128]
__device__ float g_kmax_part[16384];                       // [32][512] (128 used)
__device__ float g_kmax[32];
__device__ float g_ksum[8192];                             // [32][256]
__device__ float g_vsum[2048];                             // [32][64]
__device__ float g_ctx[524288];                            // [32][256][64]
__device__ float g_wpT[65536];
__device__ float g_wopT[131072];
__device__ float g_b2[256];
__device__ float g_s[256];

// ================= helpers =================
__device__ __forceinline__ uint32_t pk16(uint16_t a, uint16_t b) {
    return (uint32_t)a | ((uint32_t)b << 16);
}
__device__ __forceinline__ void spbf(float x, uint16_t& h, uint16_t& l) {
    __nv_bfloat16 hb = __float2bfloat16_rn(x);
    h = __bfloat16_as_ushort(hb);
    l = __bfloat16_as_ushort(__float2bfloat16_rn(x - __bfloat162float(hb)));
}
__device__ __forceinline__ float fbf16(uint16_t u) {
    return __bfloat162float(__ushort_as_bfloat16(u));
}
__device__ __forceinline__ uint16_t f16u(float x) {
    return __half_as_ushort(__float2half_rn(x));
}
__device__ __forceinline__ float uf16(uint16_t u) {
    return __half2float(__ushort_as_half(u));
}
__device__ __forceinline__ void mma_bf16(float* c, const uint32_t* a, const uint32_t* b) {
    asm volatile(
        "mma.sync.aligned.m16n8k16.row.col.f32.bf16.bf16.f32 "
        "{%0,%1,%2,%3}, {%4,%5,%6,%7}, {%8,%9}, {%0,%1,%2,%3};"
        : "+f"(c[0]), "+f"(c[1]), "+f"(c[2]), "+f"(c[3])
        : "r"(a[0]), "r"(a[1]), "r"(a[2]), "r"(a[3]), "r"(b[0]), "r"(b[1]));
}
__device__ __forceinline__ void mma_f16(float* c, const uint32_t* a, const uint32_t* b) {
    asm volatile(
        "mma.sync.aligned.m16n8k16.row.col.f32.f16.f16.f32 "
        "{%0,%1,%2,%3}, {%4,%5,%6,%7}, {%8,%9}, {%0,%1,%2,%3};"
        : "+f"(c[0]), "+f"(c[1]), "+f"(c[2]), "+f"(c[3])
        : "r"(a[0]), "r"(a[1]), "r"(a[2]), "r"(a[3]), "r"(b[0]), "r"(b[1]));
}
__device__ __forceinline__ uint32_t s2u(const void* p) {
    return (uint32_t)__cvta_generic_to_shared(p);
}
__device__ __forceinline__ void ldm_x4(uint32_t* r, uint32_t addr) {
    asm volatile("ldmatrix.sync.aligned.m8n8.x4.shared.b16 {%0,%1,%2,%3}, [%4];"
        : "=r"(r[0]), "=r"(r[1]), "=r"(r[2]), "=r"(r[3]) : "r"(addr));
}
__device__ __forceinline__ void cpa16(uint32_t dst, const void* src) {
    asm volatile("cp.async.ca.shared.global [%0], [%1], 16;" :: "r"(dst), "l"(src));
}
__device__ __forceinline__ void cpa_commit() { asm volatile("cp.async.commit_group;"); }
template <int N> __device__ __forceinline__ void cpa_wait() {
    asm volatile("cp.async.wait_group %0;" :: "n"(N));
}

// ============= pre-split cp.async+ldmatrix GEMM (verified R12) =============
#define GLD 20
__device__ __forceinline__ void gemm2_issue(
    const uint32_t* pA0, const uint32_t* pA1,
    const uint32_t* pB0, const uint32_t* pB1,
    int Ku, int row0, int col0, int st, int stage,
    uint32_t sbase, int tid) {
#pragma unroll
    for (int i = 0; i < 8; i++) {
        int u = tid + i * 256;
        int pl = u >> 9;
        int t = u & 511;
        int row = t >> 2, c4 = (t & 3) * 4;
        const uint32_t* src;
        if (pl == 0)      src = pA0 + (size_t)(row0 + row) * Ku + st * 16 + c4;
        else if (pl == 1) src = pA1 + (size_t)(row0 + row) * Ku + st * 16 + c4;
        else if (pl == 2) src = pB0 + (size_t)(col0 + row) * Ku + st * 16 + c4;
        else              src = pB1 + (size_t)(col0 + row) * Ku + st * 16 + c4;
        uint32_t dst = sbase + (uint32_t)(stage * 10240 + pl * 2560 + row * GLD + c4) * 4;
        cpa16(dst, src);
    }
    cpa_commit();
}

__global__ void __launch_bounds__(256) gemm2(
    int K, int qkv_mode, const float* __restrict__ btab, float* __restrict__ dout) {
    extern __shared__ uint32_t gsm[];
    const uint32_t sbase = s2u(gsm);
    const int tid = threadIdx.x;
    const int wid = tid >> 5, lane = tid & 31;
    const int lr = lane >> 2, tig = lane & 3;
    const int m0 = (wid & 3) * 32;
    const int n0 = (wid >> 2) * 64;
    const int row0 = blockIdx.y * 128;
    const int col0 = blockIdx.x * 128;

    const uint32_t *pA0, *pA1, *pB0, *pB1;
    if (qkv_mode) {
        pA0 = g_xh; pA1 = g_xl;
        pB0 = g_wTh + (size_t)blockIdx.z * 65536;
        pB1 = g_wTl + (size_t)blockIdx.z * 65536;
    } else {
        pA0 = g_attnh; pA1 = g_attnl;
        pB0 = g_wopTh; pB1 = g_wopTl;
    }
    const int Ku = K >> 1;
    const int steps = K >> 5;

    float c[2][8][4];
#pragma unroll
    for (int i = 0; i < 2; i++)
#pragma unroll
        for (int j = 0; j < 8; j++)
#pragma unroll
            for (int t = 0; t < 4; t++) c[i][j][t] = 0.f;

    gemm2_issue(pA0, pA1, pB0, pB1, Ku, row0, col0, 0, 0, sbase, tid);

    for (int st = 0; st < steps; st++) {
        if (st + 1 < steps) {
            gemm2_issue(pA0, pA1, pB0, pB1, Ku, row0, col0, st + 1, (st + 1) & 1, sbase, tid);
            cpa_wait<1>();
        } else {
            cpa_wait<0>();
        }
        __syncthreads();
        const uint32_t stoff = (uint32_t)((st & 1) * 10240) * 4;
        const uint32_t AhB = sbase + stoff;
        const uint32_t AlB = AhB + 2560 * 4;
        const uint32_t BhB = AhB + 5120 * 4;
        const uint32_t BlB = AhB + 7680 * 4;
#pragma unroll
        for (int ks = 0; ks < 2; ks++) {
            uint32_t ah[2][4], al[2][4];
#pragma unroll
            for (int i = 0; i < 2; i++) {
                uint32_t ro = (uint32_t)((m0 + i * 16 + (lane & 15)) * GLD) * 4
                              + ks * 32 + (lane >> 4) * 16;
                ldm_x4(ah[i], AhB + ro);
                ldm_x4(al[i], AlB + ro);
            }
#pragma unroll
            for (int jg = 0; jg < 4; jg++) {
                uint32_t ro = (uint32_t)((n0 + jg * 16 + (lane & 15)) * GLD) * 4
                              + ks * 32 + (lane >> 4) * 16;
                uint32_t bh4[4], bl4[4];
                ldm_x4(bh4, BhB + ro);
                ldm_x4(bl4, BlB + ro);
                uint32_t b0h[2] = { bh4[0], bh4[2] }, b1h[2] = { bh4[1], bh4[3] };
                uint32_t b0l[2] = { bl4[0], bl4[2] }, b1l[2] = { bl4[1], bl4[3] };
#pragma unroll
                for (int i = 0; i < 2; i++) {
                    mma_bf16(c[i][jg * 2],     ah[i], b0h);
                    mma_bf16(c[i][jg * 2],     ah[i], b0l);
                    mma_bf16(c[i][jg * 2],     al[i], b0h);
                    mma_bf16(c[i][jg * 2 + 1], ah[i], b1h);
                    mma_bf16(c[i][jg * 2 + 1], ah[i], b1l);
                    mma_bf16(c[i][jg * 2 + 1], al[i], b1h);
                }
            }
        }
        __syncthreads();
    }

#pragma unroll
    for (int i = 0; i < 2; i++) {
#pragma unroll
        for (int rr = 0; rr < 2; rr++) {
            const int r = row0 + m0 + i * 16 + lr + rr * 8;
            if (qkv_mode) {
                const int b = r >> 14, n = r & (NTOK - 1);
                const int z = blockIdx.z;
                if (z < 2) {
                    uint32_t* ph = z == 0 ? g_qh : g_kh;
                    uint32_t* pl = z == 0 ? g_ql : g_kl;
#pragma unroll
                    for (int j = 0; j < 8; j++) {
                        const int cg = col0 + n0 + j * 8 + tig * 2;
                        const int hh = cg >> 6, off = cg & 63;
                        size_t di = ((size_t)(b * 8 + hh) * NTOK + n) * 32 + (off >> 1);
                        uint16_t h0, l0, h1, l1;
                        spbf(c[i][j][rr * 2], h0, l0);
                        spbf(c[i][j][rr * 2 + 1], h1, l1);
                        ph[di] = pk16(h0, h1);
                        pl[di] = pk16(l0, l1);
                    }
                } else {
#pragma unroll
                    for (int j = 0; j < 8; j++) {
                        const int cg = col0 + n0 + j * 8 + tig * 2;
                        const int hh = cg >> 6, off = cg & 63;
                        float* dp = g_v + ((size_t)(b * 8 + hh) * NTOK + n) * 64 + off;
                        *(float2*)dp = make_float2(c[i][j][rr * 2], c[i][j][rr * 2 + 1]);
                    }
                }
            } else {
                const int n = r & (NTOK - 1);
                const int ii = n >> 7, jc = n & 127;
                int rel = ii - jc;
                rel = rel < -7 ? -7 : (rel > 7 ? 7 : rel);
                const float brow = btab[rel + 7];
#pragma unroll
                for (int j = 0; j < 8; j++) {
                    const int cg = col0 + n0 + j * 8 + tig * 2;
                    float2 b2v = *(const float2*)(g_b2 + cg);
                    float2 sv  = *(const float2*)(g_s + cg);
                    float* dp = dout + (size_t)r * 256 + cg;
                    *(float2*)dp = make_float2(c[i][j][rr * 2]     + b2v.x + brow * sv.x,
                                               c[i][j][rr * 2 + 1] + b2v.y + brow * sv.y);
                }
            }
        }
    }
}

// ============= phi via mma (split-3): dd = q @ (DN*proj)^T =============
// mode 1: query -> exp(row max) -> g_qpf16
// mode 0: key   -> block max -> kmax_part, write e_b = ratio*exp(dd-diag-mb) -> g_kpf16
#define PLDA 36
__global__ void __launch_bounds__(256) phi_mma(const float* __restrict__ proj,
                                               int mode) {
    extern __shared__ uint32_t sm[];
    uint32_t* sAh = sm;
    uint32_t* sAl = sAh + 128 * PLDA;
    uint32_t* sBh = sAl + 128 * PLDA;
    uint32_t* sBl = sBh + 256 * PLDA;
    float* s_diag = (float*)(sBl + 256 * PLDA);
    float* s_rmax = s_diag + 128;

    const int tid = threadIdx.x;
    const int wid = tid >> 5, lane = tid & 31;
    const int lr = lane >> 2, tig = lane & 3;
    const int m0 = (wid & 3) * 32;
    const int n0 = (wid >> 2) * 128;
    const int bh = blockIdx.y;
    const int row0 = blockIdx.x * 128;
    const uint32_t* ph = (mode == 1) ? g_qh : g_kh;
    const uint32_t* pl = (mode == 1) ? g_ql : g_kl;

#pragma unroll
    for (int i = 0; i < 16; i++) {
        int u = tid + i * 256;
        int f = u >> 4, c4 = u & 15;
        float4 v = ((const float4*)proj)[u];
        v.x *= DN; v.y *= DN; v.z *= DN; v.w *= DN;
        uint16_t h0, h1, h2, h3, l0, l1, l2, l3;
        spbf(v.x, h0, l0); spbf(v.y, h1, l1); spbf(v.z, h2, l2); spbf(v.w, h3, l3);
        sBh[f * PLDA + c4 * 2]     = pk16(h0, h1);
        sBh[f * PLDA + c4 * 2 + 1] = pk16(h2, h3);
        sBl[f * PLDA + c4 * 2]     = pk16(l0, l1);
        sBl[f * PLDA + c4 * 2 + 1] = pk16(l2, l3);
    }
#pragma unroll
    for (int i = 0; i < 16; i++) {
        int u = tid + i * 256;
        int r = u >> 5, cc = u & 31;
        size_t gi = ((size_t)bh * NTOK + row0 + r) * 32 + cc;
        uint32_t vh = ph[gi], vl = pl[gi];
        sAh[r * PLDA + cc] = vh;
        sAl[r * PLDA + cc] = vl;
        float e0 = fbf16((uint16_t)(vh & 0xFFFF)) + fbf16((uint16_t)(vl & 0xFFFF));
        float e1 = fbf16((uint16_t)(vh >> 16)) + fbf16((uint16_t)(vl >> 16));
        float ds = e0 * e0 + e1 * e1;
#pragma unroll
        for (int o = 1; o < 32; o <<= 1) ds += __shfl_xor_sync(0xffffffffu, ds, o);
        if (lane == 0) s_diag[r] = 0.0625f * ds;   // 0.5*DN^2*|q|^2
    }
    __syncthreads();

    float c[2][16][4];
#pragma unroll
    for (int i = 0; i < 2; i++)
#pragma unroll
        for (int j = 0; j < 16; j++)
#pragma unroll
            for (int t = 0; t < 4; t++) c[i][j][t] = 0.f;

#pragma unroll
    for (int ks = 0; ks < 4; ks++) {
        const int kb = ks * 8 + tig;
        uint32_t ah[2][4], al[2][4];
#pragma unroll
        for (int i = 0; i < 2; i++) {
            int b0 = (m0 + i * 16 + lr) * PLDA + kb;
            ah[i][0] = sAh[b0];             ah[i][1] = sAh[b0 + 8 * PLDA];
            ah[i][2] = sAh[b0 + 4];         ah[i][3] = sAh[b0 + 8 * PLDA + 4];
            al[i][0] = sAl[b0];             al[i][1] = sAl[b0 + 8 * PLDA];
            al[i][2] = sAl[b0 + 4];         al[i][3] = sAl[b0 + 8 * PLDA + 4];
        }
#pragma unroll
        for (int j = 0; j < 16; j++) {
            int nb = (n0 + j * 8 + lr) * PLDA + kb;
            uint32_t bh2[2] = { sBh[nb], sBh[nb + 4] };
            uint32_t bl2[2] = { sBl[nb], sBl[nb + 4] };
            mma_bf16(c[0][j], ah[0], bh2);
            mma_bf16(c[1][j], ah[1], bh2);
            mma_bf16(c[0][j], ah[0], bl2);
            mma_bf16(c[1][j], ah[1], bl2);
            mma_bf16(c[0][j], al[0], bh2);
            mma_bf16(c[1][j], al[1], bh2);
        }
    }

    if (mode == 0) {
        // key: block max, publish, then write e_b scaled by block max
        float bm = -1e30f;
#pragma unroll
        for (int i = 0; i < 2; i++)
#pragma unroll
            for (int j = 0; j < 16; j++)
#pragma unroll
                for (int t = 0; t < 4; t++) bm = fmaxf(bm, c[i][j][t]);
#pragma unroll
        for (int o = 16; o >= 1; o >>= 1) bm = fmaxf(bm, __shfl_xor_sync(0xffffffffu, bm, o));
        if (lane == 0) s_rmax[wid] = bm;
        __syncthreads();
        float mb = s_rmax[0];
#pragma unroll
        for (int w = 1; w < 8; w++) mb = fmaxf(mb, s_rmax[w]);
        if (tid == 0) g_kmax_part[bh * 512 + blockIdx.x] = mb;
#pragma unroll
        for (int i = 0; i < 2; i++)
#pragma unroll
            for (int rr = 0; rr < 2; rr++) {
                const int r = m0 + i * 16 + lr + rr * 8;
                const float dia = s_diag[r];
                uint32_t* dst = g_kpf16 + ((size_t)bh * NTOK + row0 + r) * 128 + (n0 >> 1);
#pragma unroll
                for (int j = 0; j < 16; j++) {
                    float v0 = RATIO * expf(c[i][j][rr * 2]     - dia - mb);
                    float v1 = RATIO * expf(c[i][j][rr * 2 + 1] - dia - mb);
                    dst[j * 4 + tig] = pk16(f16u(v0), f16u(v1));
                }
            }
    } else {
        // query: per-row max across 2 col-warps, then exp + eps
#pragma unroll
        for (int i = 0; i < 2; i++)
#pragma unroll
            for (int rr = 0; rr < 2; rr++) {
                float mx = -1e30f;
#pragma unroll
                for (int j = 0; j < 16; j++) {
                    mx = fmaxf(mx, c[i][j][rr * 2]);
                    mx = fmaxf(mx, c[i][j][rr * 2 + 1]);
                }
                mx = fmaxf(mx, __shfl_xor_sync(0xffffffffu, mx, 1));
                mx = fmaxf(mx, __shfl_xor_sync(0xffffffffu, mx, 2));
                if (tig == 0)
                    s_rmax[(wid >> 2) * 128 + m0 + i * 16 + lr + rr * 8] = mx;
            }
        __syncthreads();
#pragma unroll
        for (int i = 0; i < 2; i++)
#pragma unroll
            for (int rr = 0; rr < 2; rr++) {
                const int r = m0 + i * 16 + lr + rr * 8;
                const float m = fmaxf(s_rmax[r], s_rmax[128 + r]);
                const float dia = s_diag[r];
                uint32_t* dst = g_qpf16 + ((size_t)bh * NTOK + row0 + r) * 128 + (n0 >> 1);
#pragma unroll
                for (int j = 0; j < 16; j++) {
                    float v0 = RATIO * (expf(c[i][j][rr * 2]     - dia - m) + FEPS);
                    float v1 = RATIO * (expf(c[i][j][rr * 2 + 1] - dia - m) + FEPS);
                    dst[j * 4 + tig] = pk16(f16u(v0), f16u(v1));
                }
            }
    }
}

__global__ void kmax_reduce() {
    __shared__ float s[8];
    int bh = blockIdx.x, tid = threadIdx.x;
    float v = (tid < 128) ? g_kmax_part[bh * 512 + tid] : -1e30f;
#pragma unroll
    for (int o = 1; o < 32; o <<= 1) v = fmaxf(v, __shfl_xor_sync(0xffffffffu, v, o));
    if ((tid & 31) == 0) s[tid >> 5] = v;
    __syncthreads();
    if (tid == 0) {
        float m = s[0];
#pragma unroll
        for (int w = 1; w < 8; w++) m = fmaxf(m, s[w]);
        g_kmax[bh] = m;
    }
}

// ============= ctx via mma (fp16): C[f][d] += e_b @ (v*s)^T; fused ksum,vsum =============
__global__ void __launch_bounds__(256) ctx_mma() {
    extern __shared__ uint32_t csm[];
    uint32_t* sStage = csm;              // 32 * 129 (kp tile raw, padded)
    uint32_t* sA = sStage + 32 * 129;    // 256 * 20 (fp16 pairs over n)
    uint32_t* sB = sA + 5120;            // 64 * 20
    float* sv = (float*)(sB + 1280);     // 32 * 68
    float* s_s = sv + 32 * 68;           // 16 per-block scales
    const int tid = threadIdx.x;
    const int wid = tid >> 5, lane = tid & 31;
    const int lr = lane >> 2, tig = lane & 3;
    const int m0 = (wid & 3) * 64;
    const int n0w = (wid >> 2) * 32;
    const int bh = blockIdx.y;
    const int kc = blockIdx.x;

    if (tid < 16) {
        float mg = g_kmax[bh];
        s_s[tid] = expf(g_kmax_part[bh * 512 + kc * 16 + tid] - mg);
    }

    float c[4][4][4];
#pragma unroll
    for (int i = 0; i < 4; i++)
#pragma unroll
        for (int j = 0; j < 4; j++)
#pragma unroll
            for (int t = 0; t < 4; t++) c[i][j][t] = 0.f;
    float fsum[16];
#pragma unroll
    for (int i = 0; i < 16; i++) fsum[i] = 0.f;
    float vsum[4];
#pragma unroll
    for (int i = 0; i < 4; i++) vsum[i] = 0.f;

    const int fA = tid >> 4;       // 0..15
    const int npA = tid & 15;
    __syncthreads();

    for (int nc = 0; nc < 64; nc++) {
        const int nbase = kc * 2048 + nc * 32;
        const float s_tile = s_s[nc >> 2];
        // stage kp tile [32n][128w] raw (coalesced)
#pragma unroll
        for (int i = 0; i < 16; i++) {
            int u = tid + i * 256;
            int n = u >> 7, cw = u & 127;
            sStage[n * 129 + cw] = g_kpf16[((size_t)bh * NTOK + nbase + n) * 128 + cw];
        }
        // v tile [32][64] fp32
#pragma unroll
        for (int i = 0; i < 2; i++) {
            int u = tid + i * 256;
            int n = u >> 4, c4 = u & 15;
            *(float4*)&sv[n * 68 + c4 * 4] =
                *(const float4*)(g_v + ((size_t)bh * NTOK + nbase + n) * 64 + c4 * 4);
        }
        __syncthreads();
        // build A [256f][16 n-pairs] + fused weighted ksum
        {
            const uint16_t* st16 = (const uint16_t*)sStage;
#pragma unroll
            for (int i = 0; i < 16; i++) {
                int f = fA + i * 16;
                uint16_t a0 = st16[(2 * npA) * 258 + f];
                uint16_t a1 = st16[(2 * npA + 1) * 258 + f];
                sA[f * 20 + npA] = pk16(a0, a1);
                fsum[i] += (uf16(a0) + uf16(a1)) * s_tile;
            }
        }
        // build B [64d][16 n-pairs] = fp16(v*s_tile); fused raw vsum
#pragma unroll
        for (int i = 0; i < 4; i++) {
            int u = tid + i * 256;
            int d = u >> 4, nw = u & 15;
            float v0 = sv[(nw * 2) * 68 + d];
            float v1 = sv[(nw * 2 + 1) * 68 + d];
            sB[d * 20 + nw] = pk16(f16u(v0 * s_tile), f16u(v1 * s_tile));
            vsum[i] += v0 + v1;
        }
        __syncthreads();
#pragma unroll
        for (int ks = 0; ks < 2; ks++) {
            const int kb = ks * 8 + tig;
            uint32_t a[4][4];
#pragma unroll
            for (int i = 0; i < 4; i++) {
                int b0 = (m0 + i * 16 + lr) * 20 + kb;
                a[i][0] = sA[b0];       a[i][1] = sA[b0 + 160];
                a[i][2] = sA[b0 + 4];   a[i][3] = sA[b0 + 164];
            }
#pragma unroll
            for (int j = 0; j < 4; j++) {
                int nb = (n0w + j * 8 + lr) * 20 + kb;
                uint32_t b2[2] = { sB[nb], sB[nb + 4] };
#pragma unroll
                for (int i = 0; i < 4; i++) mma_f16(c[i][j], a[i], b2);
            }
        }
        __syncthreads();
    }
    // ctx atomics
#pragma unroll
    for (int i = 0; i < 4; i++)
#pragma unroll
        for (int j = 0; j < 4; j++)
#pragma unroll
            for (int rr = 0; rr < 2; rr++) {
                int fr = m0 + i * 16 + lr + rr * 8;
                int d = n0w + j * 8 + tig * 2;
                atomicAdd(&g_ctx[((size_t)bh * 256 + fr) * 64 + d], c[i][j][rr * 2]);
                atomicAdd(&g_ctx[((size_t)bh * 256 + fr) * 64 + d + 1], c[i][j][rr * 2 + 1]);
            }
    // ksum: reduce over the 16 lanes sharing f-set
#pragma unroll
    for (int o = 1; o < 16; o <<= 1)
#pragma unroll
        for (int i = 0; i < 16; i++)
            fsum[i] += __shfl_xor_sync(0xffffffffu, fsum[i], o);
    if ((lane & 15) == 0) {
#pragma unroll
        for (int i = 0; i < 16; i++)
            atomicAdd(&g_ksum[bh * 256 + fA + i * 16], fsum[i]);
    }
    // vsum: reduce over 16 threads sharing d-set (tid>>4 groups = 16-lane groups)
#pragma unroll
    for (int o = 1; o < 16; o <<= 1)
#pragma unroll
        for (int i = 0; i < 4; i++)
            vsum[i] += __shfl_xor_sync(0xffffffffu, vsum[i], o);
    if ((lane & 15) == 0) {
        int d0 = tid >> 4;
#pragma unroll
        for (int i = 0; i < 4; i++)
            atomicAdd(&g_vsum[bh * 64 + d0 + i * 16], vsum[i]);
    }
}

// ctxT + eps-constant fixups (ctx += CEPS*vsum[d], ksum += CEPS*NTOK)
__global__ void ctxT_kernel() {
    const int bh = blockIdx.x, tid = threadIdx.x;
    g_ksum[bh * 256 + tid] += CEPS * (float)NTOK;
    for (int i = 0; i < 64; i++) {
        int u = tid + i * 256;
        int f = u >> 6, d = u & 63;
        float v = g_ctx[((size_t)bh * 256 + f) * 64 + d] + CEPS * g_vsum[bh * 64 + d];
        ((uint16_t*)g_ctxTf16)[(size_t)bh * 16384 + d * 256 + f] = f16u(v);
    }
}

// ============= attn via mma (fp16 single) + fused d_inv, bf16-split output =============
__global__ void __launch_bounds__(256) attn_mma() {
    __shared__ uint32_t sA[128 * 20];
    __shared__ uint32_t sB[64 * 20];
    __shared__ float sk[32];
    __shared__ float sdsum[128];
    const int tid = threadIdx.x;
    const int wid = tid >> 5, lane = tid & 31;
    const int lr = lane >> 2, tig = lane & 3;
    const int m0 = (wid & 3) * 32;
    const int n0w = (wid >> 2) * 32;
    const int bh = blockIdx.y;
    const int row0 = blockIdx.x * 128;

    float c[2][4][4];
#pragma unroll
    for (int i = 0; i < 2; i++)
#pragma unroll
        for (int j = 0; j < 4; j++)
#pragma unroll
            for (int t = 0; t < 4; t++) c[i][j][t] = 0.f;
    float dsum = 0.f;

    for (int fc = 0; fc < 8; fc++) {
#pragma unroll
        for (int i = 0; i < 8; i++) {
            int u = tid + i * 256;
            int n = u >> 4, cw = u & 15;
            sA[n * 20 + cw] = g_qpf16[((size_t)bh * NTOK + row0 + n) * 128 + fc * 16 + cw];
        }
#pragma unroll
        for (int i = 0; i < 4; i++) {
            int u = tid + i * 256;
            int d = u >> 4, cw = u & 15;
            sB[d * 20 + cw] = g_ctxTf16[(size_t)bh * 8192 + d * 128 + fc * 16 + cw];
        }
        if (tid < 32) sk[tid] = g_ksum[bh * 256 + fc * 32 + tid];
        __syncthreads();
        if (tid < 128) {
#pragma unroll
            for (int w = 0; w < 16; w++) {
                uint32_t p = sA[tid * 20 + w];
                dsum += uf16((uint16_t)(p & 0xFFFF)) * sk[w * 2]
                      + uf16((uint16_t)(p >> 16)) * sk[w * 2 + 1];
            }
        }
#pragma unroll
        for (int ks = 0; ks < 2; ks++) {
            const int kb = ks * 8 + tig;
            uint32_t a[2][4];
#pragma unroll
            for (int i = 0; i < 2; i++) {
                int b0 = (m0 + i * 16 + lr) * 20 + kb;
                a[i][0] = sA[b0];       a[i][1] = sA[b0 + 160];
                a[i][2] = sA[b0 + 4];   a[i][3] = sA[b0 + 164];
            }
#pragma unroll
            for (int j = 0; j < 4; j++) {
                int nb = (n0w + j * 8 + lr) * 20 + kb;
                uint32_t b2[2] = { sB[nb], sB[nb + 4] };
#pragma unroll
                for (int i = 0; i < 2; i++) mma_f16(c[i][j], a[i], b2);
            }
        }
        __syncthreads();
    }
    if (tid < 128) sdsum[tid] = dsum;
    __syncthreads();

    const int b = bh >> 3, h = bh & 7;
#pragma unroll
    for (int i = 0; i < 2; i++)
#pragma unroll
        for (int rr = 0; rr < 2; rr++) {
            const int r = m0 + i * 16 + lr + rr * 8;
            const float rinv = 1.0f / sdsum[r];
            const int n = row0 + r;
            size_t rowbase = ((size_t)b * NTOK + n) * 256 + ((h * 64 + n0w) >> 1);
#pragma unroll
            for (int j = 0; j < 4; j++) {
                uint16_t h0, l0, h1, l1;
                spbf(c[i][j][rr * 2] * rinv, h0, l0);
                spbf(c[i][j][rr * 2 + 1] * rinv, h1, l1);
                g_attnh[rowbase + j * 4 + tig] = pk16(h0, h1);
                g_attnl[rowbase + j * 4 + tig] = pk16(l0, l1);
            }
        }
}

// ---------------- prep kernels ----------------
__global__ void zero_accum() {
    int idx = blockIdx.x * 256 + threadIdx.x;
    if (idx < 524288) g_ctx[idx] = 0.f;
    else if (idx < 524288 + 8192) g_ksum[idx - 524288] = 0.f;
    else if (idx < 524288 + 8192 + 2048) g_vsum[idx - 524288 - 8192] = 0.f;
}

__global__ void split_x(const float* __restrict__ x) {
    int idx = blockIdx.x * 256 + threadIdx.x;
    int row = idx >> 7, cp = idx & 127;
    float v0 = x[(size_t)row * 256 + 2 * cp];
    float v1 = x[(size_t)row * 256 + 2 * cp + 1];
    uint16_t h0, l0, h1, l1;
    spbf(v0, h0, l0); spbf(v1, h1, l1);
    g_xh[idx] = pk16(h0, h1);
    g_xl[idx] = pk16(l0, l1);
}

__global__ void wt_split(const float* __restrict__ Wq, const float* __restrict__ Wk,
                         const float* __restrict__ Wv) {
    int idx = blockIdx.x * 256 + threadIdx.x;
    int z = idx >> 16;
    int rem = idx & 65535;
    int n = rem >> 7, cp = rem & 127;
    const float* W = z == 0 ? Wq : (z == 1 ? Wk : Wv);
    float v0 = W[(size_t)(2 * cp) * 512 + n];
    float v1 = W[(size_t)(2 * cp + 1) * 512 + n];
    uint16_t h0, l0, h1, l1;
    spbf(v0, h0, l0); spbf(v1, h1, l1);
    g_wTh[idx] = pk16(h0, h1);
    g_wTl[idx] = pk16(l0, l1);
}

__global__ void wpT_kernel(const float* __restrict__ Wp) {
    int idx = blockIdx.x * 256 + threadIdx.x;
    int n = idx >> 8, c = idx & 255;
    g_wpT[idx] = Wp[c * 256 + n];
}

__global__ void wowp_kernel(const float* __restrict__ Wo) {
    __shared__ float swo[256];
    int k = blockIdx.x, n = threadIdx.x;
    swo[n] = Wo[(size_t)k * 256 + n];
    __syncthreads();
    float acc = 0.f;
    const float* wp = g_wpT + n * 256;
#pragma unroll 4
    for (int cc = 0; cc < 256; cc += 4) {
        float4 a = *(const float4*)(swo + cc);
        float4 bb = *(const float4*)(wp + cc);
        acc += a.x * bb.x + a.y * bb.y + a.z * bb.z + a.w * bb.w;
    }
    g_wopT[n * 512 + k] = acc;
}

__global__ void wopT_split() {
    int idx = blockIdx.x * 256 + threadIdx.x;
    int n = idx >> 8, cp = idx & 255;
    float v0 = g_wopT[n * 512 + 2 * cp];
    float v1 = g_wopT[n * 512 + 2 * cp + 1];
    uint16_t h0, l0, h1, l1;
    spbf(v0, h0, l0); spbf(v1, h1, l1);
    g_wopTh[idx] = pk16(h0, h1);
    g_wopTl[idx] = pk16(l0, l1);
}

__global__ void b2s_kernel(const float* __restrict__ bo, const float* __restrict__ bp) {
    int n = threadIdx.x;
    float a = 0.f, ssum = 0.f;
    const float* wp = g_wpT + n * 256;
    for (int cc = 0; cc < 256; cc++) {
        float w = wp[cc];
        a += bo[cc] * w;
        ssum += w;
    }
    g_b2[n] = a + bp[n];
    g_s[n] = ssum;
}

// ---------------- launch ----------------
extern "C" void kernel_launch(void* const* d_in, const int* in_sizes, int n_in,
                              void* d_out, int out_size) {
    (void)in_sizes; (void)n_in; (void)out_size;
    const float* x    = (const float*)d_in[0];
    const float* Wq   = (const float*)d_in[1];
    const float* Wk   = (const float*)d_in[2];
    const float* Wv   = (const float*)d_in[3];
    const float* Wo   = (const float*)d_in[4];
    const float* bo   = (const float*)d_in[5];
    const float* proj = (const float*)d_in[6];
    const float* Wp   = (const float*)d_in[7];
    const float* bp   = (const float*)d_in[8];
    const float* btab = (const float*)d_in[9];
    float* out = (float*)d_out;

    cudaFuncSetAttribute(gemm2, cudaFuncAttributeMaxDynamicSharedMemorySize, 81920);
    cudaFuncSetAttribute(phi_mma, cudaFuncAttributeMaxDynamicSharedMemorySize, 112128);
    cudaFuncSetAttribute(ctx_mma, cudaFuncAttributeMaxDynamicSharedMemorySize, 50944);

    zero_accum<<<2088, 256>>>();
    split_x<<<32768, 256>>>(x);
    wt_split<<<768, 256>>>(Wq, Wk, Wv);
    wpT_kernel<<<256, 256>>>(Wp);
    wowp_kernel<<<512, 256>>>(Wo);
    wopT_split<<<256, 256>>>();
    b2s_kernel<<<1, 256>>>(bo, bp);

    gemm2<<<dim3(4, 512, 3), 256, 81920>>>(256, 1, nullptr, nullptr);

    phi_mma<<<dim3(128, 32), 256, 112128>>>(proj, 1);   // query -> qp fp16
    phi_mma<<<dim3(128, 32), 256, 112128>>>(proj, 0);   // key -> e_b fp16 + block max
    kmax_reduce<<<32, 256>>>();
    ctx_mma<<<dim3(8, 32), 256, 50944>>>();
    ctxT_kernel<<<32, 256>>>();
    attn_mma<<<dim3(128, 32), 256>>>();

    gemm2<<<dim3(2, 512, 1), 256, 81920>>>(512, 0, btab, out);
}